// round 5
// baseline (speedup 1.0000x reference)
#include <cuda_runtime.h>
#include <cuda_bf16.h>
#include <math.h>
#include <stdint.h>

#define NBATCH 4
#define NCH    180
#define IMG    256
#define NPIX   (IMG*IMG)            // 65536
#define TOTPIX (NBATCH*NPIX)        // 262144
#define MIDC   36
#define NWIN   1024

// ---- scratch (device globals; no allocation allowed) ----
__device__ float g_h1[(size_t)TOTPIX*MIDC];
__device__ float g_h2[(size_t)TOTPIX*MIDC];
__device__ float g_qv[(size_t)TOTPIX*NCH];
__device__ float g_y [(size_t)TOTPIX*NCH];
__device__ float g_pos[961*6];
__device__ float g_rpb[6*256*64];
// packed bf16 weights, transposed [n][k] padded tiles
// 180x180 weights: 6 chunks (Bh0,Bh1,Bh2,Bl0,Bl1,Bl2), each [192][72]
__device__ __align__(16) __nv_bfloat16 g_pk_lw[6*13824];
__device__ __align__(16) __nv_bfloat16 g_pk_pj[6*13824];
// w3 (36x180): 2 chunks (hi,lo), each [192][56]
__device__ __align__(16) __nv_bfloat16 g_pk_w3[2*10752];

typedef unsigned long long u64;

__device__ __forceinline__ u64 pk2(float lo, float hi){
  u64 r; asm("mov.b64 %0,{%1,%2};" : "=l"(r) : "f"(lo), "f"(hi)); return r;
}
__device__ __forceinline__ u64 dup2(float v){ return pk2(v, v); }
__device__ __forceinline__ void up2(u64 v, float& lo, float& hi){
  asm("mov.b64 {%0,%1},%2;" : "=f"(lo), "=f"(hi) : "l"(v));
}
__device__ __forceinline__ u64 ffma2(u64 a, u64 b, u64 c){
  u64 d; asm("fma.rn.f32x2 %0,%1,%2,%3;" : "=l"(d) : "l"(a), "l"(b), "l"(c)); return d;
}
__device__ __forceinline__ u64 fmul2(u64 a, u64 b){
  u64 d; asm("mul.rn.f32x2 %0,%1,%2;" : "=l"(d) : "l"(a), "l"(b)); return d;
}
__device__ __forceinline__ float lrelu(float v){ return v >= 0.f ? v : 0.2f*v; }

__device__ __forceinline__ void cvhl(float v, __nv_bfloat16& h, __nv_bfloat16& l){
  h = __float2bfloat16(v);
  l = __float2bfloat16(v - __bfloat162float(h));
}

// ---- portable bf16 tensor-core mma ----
#define MMA16816(c, a, b0, b1) \
  asm volatile("mma.sync.aligned.m16n8k16.row.col.f32.bf16.bf16.f32 " \
    "{%0,%1,%2,%3}, {%4,%5,%6,%7}, {%8,%9}, {%0,%1,%2,%3};" \
    : "+f"((c)[0]), "+f"((c)[1]), "+f"((c)[2]), "+f"((c)[3]) \
    : "r"((a)[0]), "r"((a)[1]), "r"((a)[2]), "r"((a)[3]), "r"(b0), "r"(b1))

// one pass: accumulate A[128][K] x B[192][K]^T into c frags (warp tile 32x96)
__device__ __forceinline__ void mma_pass(const __nv_bfloat16* __restrict__ At,
                                         const __nv_bfloat16* __restrict__ Bs,
                                         int sa, int sb, int nks,
                                         float c[2][12][4], int lane, int wm, int wn){
  for (int ks=0; ks<nks; ks++){
    int kk = ks*16 + (lane&3)*2;
    uint32_t a[2][4];
#pragma unroll
    for (int mt=0; mt<2; mt++){
      const __nv_bfloat16* ap = At + (wm*32 + mt*16 + (lane>>2))*sa + kk;
      a[mt][0] = *(const uint32_t*)ap;
      a[mt][1] = *(const uint32_t*)(ap + 8*sa);
      a[mt][2] = *(const uint32_t*)(ap + 8);
      a[mt][3] = *(const uint32_t*)(ap + 8*sa + 8);
    }
#pragma unroll
    for (int nt=0; nt<12; nt++){
      const __nv_bfloat16* bp = Bs + (wn*96 + nt*8 + (lane>>2))*sb + kk;
      uint32_t b0 = *(const uint32_t*)bp;
      uint32_t b1 = *(const uint32_t*)(bp + 8);
      MMA16816(c[0][nt], a[0], b0, b1);
      MMA16816(c[1][nt], a[1], b0, b1);
    }
  }
}

// =============== pack kernels ===============
__global__ void k_pack180(const float* __restrict__ W, int which){
  __nv_bfloat16* dst = which ? g_pk_pj : g_pk_lw;
  int idx = blockIdx.x*256 + threadIdx.x;
  if (idx >= 6*13824) return;
  int cc = idx/13824, r = idx - cc*13824, n = r/72, k = r - n*72;
  int half = cc/3, kc = cc - half*3;
  int kk = kc*64 + k;
  float v = (n<180 && k<64 && kk<180) ? W[kk*180+n] : 0.f;
  __nv_bfloat16 h, l; cvhl(v, h, l);
  dst[idx] = half ? l : h;
}
__global__ void k_pack36(const float* __restrict__ W){
  int idx = blockIdx.x*256 + threadIdx.x;
  if (idx >= 2*10752) return;
  int cc = idx/10752, r = idx - cc*10752, n = r/56, k = r - n*56;
  float v = (n<180 && k<36) ? W[k*180+n] : 0.f;
  __nv_bfloat16 h, l; cvhl(v, h, l);
  g_pk_w3[idx] = cc ? l : h;
}

// =============== K0a: position-bias MLP ===============
__device__ __forceinline__ void ln_relu11(const float* in, const float* w, const float* b, float* out){
  float m = 0.f;
#pragma unroll
  for (int j=0;j<11;j++) m += in[j];
  m *= (1.f/11.f);
  float var = 0.f;
#pragma unroll
  for (int j=0;j<11;j++){ float d = in[j]-m; var += d*d; }
  var *= (1.f/11.f);
  float inv = rsqrtf(var + 1e-5f);
#pragma unroll
  for (int j=0;j<11;j++) out[j] = fmaxf((in[j]-m)*inv*w[j] + b[j], 0.f);
}

__global__ void k_pos(const float* __restrict__ pw, const float* __restrict__ pb,
                      const float* __restrict__ ln1w, const float* __restrict__ ln1b,
                      const float* __restrict__ w1,  const float* __restrict__ b1,
                      const float* __restrict__ ln2w, const float* __restrict__ ln2b,
                      const float* __restrict__ w2,  const float* __restrict__ b2,
                      const float* __restrict__ ln3w, const float* __restrict__ ln3b,
                      const float* __restrict__ w3,  const float* __restrict__ b3){
  int n = blockIdx.x*blockDim.x + threadIdx.x;
  if (n >= 961) return;
  float i0 = (float)(n/31) - 15.f;
  float i1 = (float)(n%31) - 15.f;
  float p[11], t[11];
#pragma unroll
  for (int j=0;j<11;j++) p[j] = i0*pw[j] + i1*pw[11+j] + pb[j];
  ln_relu11(p, ln1w, ln1b, t);
#pragma unroll
  for (int k=0;k<11;k++){ float s=b1[k];
#pragma unroll
    for (int j=0;j<11;j++) s += t[j]*w1[j*11+k]; p[k]=s; }
  ln_relu11(p, ln2w, ln2b, t);
#pragma unroll
  for (int k=0;k<11;k++){ float s=b2[k];
#pragma unroll
    for (int j=0;j<11;j++) s += t[j]*w2[j*11+k]; p[k]=s; }
  ln_relu11(p, ln3w, ln3b, t);
#pragma unroll
  for (int k=0;k<6;k++){ float s=b3[k];
#pragma unroll
    for (int j=0;j<11;j++) s += t[j]*w3[j*6+k];
    g_pos[n*6+k] = s; }
}

// =============== K0b: rpb ===============
__global__ void k_rpb(){
  int idx = blockIdx.x*blockDim.x + threadIdx.x;
  if (idx >= 6*256*64) return;
  int nh = idx/16384;
  int r  = idx - nh*16384;
  int l  = r>>6;
  int m  = r&63;
  int rl = l>>4, cl = l&15;
  int mh = m>>3, mw = m&7;
  float s = 0.f;
#pragma unroll
  for (int rh=0;rh<2;rh++)
#pragma unroll
    for (int rw=0;rw<2;rw++){
      int r2 = mh*2+rh, c2 = mw*2+rw;
      int k = (rl-r2+15)*31 + (cl-c2+15);
      s += g_pos[k*6+nh];
    }
  g_rpb[idx] = 0.25f*s;
}

// =============== K1: h1 = lrelu(x @ w1 + b1) ===============
__global__ void __launch_bounds__(256) k_dfe1(const float* __restrict__ x,
                                              const float* __restrict__ w1,
                                              const float* __restrict__ b1){
  __shared__ __align__(16) float ws[180*36];
  int tid = threadIdx.x;
  for (int t=tid;t<180*36;t+=256) ws[t]=w1[t];
  __syncthreads();
  int r = blockIdx.x*256 + tid;
  int b = r>>16; int p = r&65535;
  const float* xp = x + (size_t)b*NCH*NPIX + p;
  u64 acc2[18];
#pragma unroll
  for (int q=0;q<18;q++) acc2[q] = pk2(b1[2*q], b1[2*q+1]);
  for (int ci=0;ci<180;ci++){
    u64 v2 = dup2(xp[(size_t)ci*NPIX]);
    const ulonglong2* wr = (const ulonglong2*)(ws + ci*36);
#pragma unroll
    for (int q=0;q<9;q++){
      ulonglong2 w = wr[q];
      acc2[2*q]   = ffma2(v2, w.x, acc2[2*q]);
      acc2[2*q+1] = ffma2(v2, w.y, acc2[2*q+1]);
    }
  }
  float2* dst = (float2*)(g_h1 + (size_t)r*36);
#pragma unroll
  for (int q=0;q<18;q++){
    float lo,hi; up2(acc2[q], lo, hi);
    dst[q] = make_float2(lrelu(lo), lrelu(hi));
  }
}

// =============== K2: h2 = lrelu(conv3x3(h1)) ===============
__global__ void __launch_bounds__(256) k_conv3(const float* __restrict__ w2,
                                               const float* __restrict__ b2){
  extern __shared__ float sm2[];
  float* ins = sm2;             // 18*18*37
  float* wsh = sm2 + 11988;     // 9*36*36
  int tid = threadIdx.x;
  int b = blockIdx.z; int hy0 = blockIdx.y*16, wx0 = blockIdx.x*16;
  for (int t=tid;t<18*18*36;t+=256){
    int ci = t%36; int rc = t/36; int col = rc%18; int row = rc/18;
    int gh = hy0+row-1, gw = wx0+col-1;
    float v = 0.f;
    if (gh>=0 && gh<IMG && gw>=0 && gw<IMG)
      v = g_h1[((size_t)(b*IMG+gh)*IMG+gw)*36 + ci];
    ins[(row*18+col)*37+ci] = v;
  }
  for (int t=tid;t<9*36*36;t+=256) wsh[t] = w2[t];
  __syncthreads();
  int tx = tid&15, ty = tid>>4;
  float acc[36];
#pragma unroll
  for (int co=0;co<36;co++) acc[co] = b2[co];
  for (int dy=0;dy<3;dy++)
    for (int dx=0;dx<3;dx++){
      const float* wp = wsh + (dy*3+dx)*36*36;
      const float* ip = ins + ((ty+dy)*18 + tx+dx)*37;
      for (int ci=0;ci<36;ci++){
        float v = ip[ci];
        const float* wr = wp + ci*36;
#pragma unroll
        for (int co=0;co<36;co++) acc[co] += v*wr[co];
      }
    }
  size_t o = ((size_t)(b*IMG+hy0+ty)*IMG + wx0+tx)*36;
  float4* dst = (float4*)(g_h2 + o);
#pragma unroll
  for (int q=0;q<9;q++){
    float4 r; r.x=lrelu(acc[q*4]); r.y=lrelu(acc[q*4+1]); r.z=lrelu(acc[q*4+2]); r.w=lrelu(acc[q*4+3]);
    dst[q]=r;
  }
}

// =============== T1: t_lin: g_y = x @ lw + lb (tensor, hi/lo) ===============
// smem: A tiles 6*9216 bf16 (hi0,hi1,hi2,lo0,lo1,lo2), B chunk 13824 bf16
__global__ void __launch_bounds__(256) t_lin(const float* __restrict__ x,
                                             const float* __restrict__ lb){
  extern __shared__ __align__(16) char smc[];
  __nv_bfloat16* Ab = (__nv_bfloat16*)smc;
  __nv_bfloat16* Bs = Ab + 6*9216;
  int tid = threadIdx.x; int lane = tid&31, wid = tid>>5;
  int wm = wid&3, wn = wid>>2;
  int r0 = blockIdx.x*128; int bb = r0>>16; int p0 = r0&65535;

  for (int idx=tid; idx<192*128; idx+=256){
    int c = idx>>7, px = idx&127;
    float v = (c<180) ? x[((size_t)(bb*180+c))*NPIX + p0+px] : 0.f;
    __nv_bfloat16 h,l; cvhl(v,h,l);
    int t = c>>6, k = c&63;
    Ab[t*9216 + px*72 + k]     = h;
    Ab[(t+3)*9216 + px*72 + k] = l;
  }
  float c[2][12][4];
#pragma unroll
  for (int mt=0;mt<2;mt++)
#pragma unroll
    for (int nt=0;nt<12;nt++)
#pragma unroll
      for (int e=0;e<4;e++) c[mt][nt][e]=0.f;

  for (int i=0;i<6;i++){
    __syncthreads();
    const uint4* src = (const uint4*)(g_pk_lw + i*13824);
    uint4* dst = (uint4*)Bs;
    for (int t=tid;t<1728;t+=256) dst[t]=src[t];
    __syncthreads();
    if (i<3){
      mma_pass(Ab + i*9216,     Bs, 72, 72, 4, c, lane, wm, wn);  // Ah,Bh
      mma_pass(Ab + (3+i)*9216, Bs, 72, 72, 4, c, lane, wm, wn);  // Al,Bh
    } else {
      mma_pass(Ab + (i-3)*9216, Bs, 72, 72, 4, c, lane, wm, wn);  // Ah,Bl
    }
  }
  __syncthreads();
  float* stash = (float*)smc;  // 128*181*4 = 92672 <= A region
#pragma unroll
  for (int mt=0;mt<2;mt++){
    int r1 = wm*32 + mt*16 + (lane>>2);
#pragma unroll
    for (int nt=0;nt<12;nt++){
      int n0 = wn*96 + nt*8 + (lane&3)*2;
      if (n0 < 180){
        float bl0=__ldg(lb+n0), bl1=__ldg(lb+n0+1);
        stash[r1*181+n0]       = c[mt][nt][0]+bl0;
        stash[r1*181+n0+1]     = c[mt][nt][1]+bl1;
        stash[(r1+8)*181+n0]   = c[mt][nt][2]+bl0;
        stash[(r1+8)*181+n0+1] = c[mt][nt][3]+bl1;
      }
    }
  }
  __syncthreads();
  {
    int f = tid;
    int px = f/180, co = f - px*180;
    for (; f < 128*180; f += 256){
      g_y[(size_t)r0*180 + f] = stash[px*181+co];
      co += 256; if (co >= 180){ co -= 180; px++; if (co >= 180){ co -= 180; px++; } }
    }
  }
}

// =============== T2: t_h3: g_qv = (h2 @ w3 + b3) * g_y ===============
// smem: Ah[128][56], Al[128][56], Bh[192][56], Bl[192][56] -> 35840 bf16; stash reuses
__global__ void __launch_bounds__(256) t_h3(const float* __restrict__ b3){
  extern __shared__ __align__(16) char smc[];
  __nv_bfloat16* Ab = (__nv_bfloat16*)smc;         // hi at 0, lo at 7168
  __nv_bfloat16* Bs = Ab + 14336;                  // hi at 0, lo at 10752
  int tid = threadIdx.x; int lane = tid&31, wid = tid>>5;
  int wm = wid&3, wn = wid>>2;
  int r0 = blockIdx.x*128;

  for (int idx=tid; idx<128*48; idx+=256){
    int px = idx/48, cc = idx - px*48;
    float v = (cc<36) ? g_h2[(size_t)(r0+px)*36 + cc] : 0.f;
    __nv_bfloat16 h,l; cvhl(v,h,l);
    Ab[px*56 + cc]        = h;
    Ab[7168 + px*56 + cc] = l;
  }
  {
    const uint4* src = (const uint4*)g_pk_w3;
    uint4* dst = (uint4*)Bs;
    for (int t=tid;t<2688;t+=256) dst[t]=src[t];
  }
  __syncthreads();
  float c[2][12][4];
#pragma unroll
  for (int mt=0;mt<2;mt++)
#pragma unroll
    for (int nt=0;nt<12;nt++)
#pragma unroll
      for (int e=0;e<4;e++) c[mt][nt][e]=0.f;

  mma_pass(Ab,        Bs,        56, 56, 3, c, lane, wm, wn);  // Ah,Bh
  mma_pass(Ab + 7168, Bs,        56, 56, 3, c, lane, wm, wn);  // Al,Bh
  mma_pass(Ab,        Bs + 10752,56, 56, 3, c, lane, wm, wn);  // Ah,Bl
  __syncthreads();
  float* stash = (float*)smc;
#pragma unroll
  for (int mt=0;mt<2;mt++){
    int r1 = wm*32 + mt*16 + (lane>>2);
#pragma unroll
    for (int nt=0;nt<12;nt++){
      int n0 = wn*96 + nt*8 + (lane&3)*2;
      if (n0 < 180){
        float b30=__ldg(b3+n0), b31=__ldg(b3+n0+1);
        stash[r1*181+n0]       = c[mt][nt][0]+b30;
        stash[r1*181+n0+1]     = c[mt][nt][1]+b31;
        stash[(r1+8)*181+n0]   = c[mt][nt][2]+b30;
        stash[(r1+8)*181+n0+1] = c[mt][nt][3]+b31;
      }
    }
  }
  __syncthreads();
  {
    int f = tid;
    int px = f/180, co = f - px*180;
    for (; f < 128*180; f += 256){
      g_qv[(size_t)r0*180 + f] = stash[px*181+co] * g_y[(size_t)r0*180 + f];
      co += 256; if (co >= 180){ co -= 180; px++; if (co >= 180){ co -= 180; px++; } }
    }
  }
}

// =============== K4: per-window attention (f32x2 scalar) ===============
__global__ void __launch_bounds__(256) k_attn(const float* __restrict__ sl_w,
                                              const float* __restrict__ sl_b){
  extern __shared__ float sm4[];
  float* QS = sm4;
  float* VS = sm4 + 256*91;
  float* SC = sm4 + 2*256*91;
  int tid = threadIdx.x;
  int bw = blockIdx.x;
  int b = bw>>8, wy = (bw>>4)&15, wx = bw&15;
  int l = tid;
  int gh = wy*16 + (l>>4), gw = wx*16 + (l&15);
  size_t pix = ((size_t)(b*IMG+gh))*IMG + gw;
  {
    const float4* src = (const float4*)(g_qv + pix*180);
#pragma unroll
    for (int k=0;k<45;k++){
      float4 v4 = src[k];
      int c0 = k*4;
      float vals[4] = {v4.x,v4.y,v4.z,v4.w};
#pragma unroll
      for (int e=0;e<4;e++){
        int c = c0+e;
        if (c < 90) QS[l*91+c] = vals[e];
        else        VS[l*91+(c-90)] = vals[e];
      }
    }
  }
  __syncthreads();
  float slw0=sl_w[0], slw1=sl_w[1], slw2=sl_w[2], slw3=sl_w[3], slb=sl_b[0];
  for (int idx=tid; idx<6144; idx+=256){
    int nh = idx>>10; int r = idx & 1023; int m = r>>4; int hd = r&15;
    float val = 0.f;
    if (hd < 15){
      int mh = m>>3, mw = m&7; int ch = nh*15+hd;
      int l00 = (mh*2)*16 + mw*2;
      val = slb + slw0*VS[l00*91+ch]      + slw1*VS[(l00+1)*91+ch]
                + slw2*VS[(l00+16)*91+ch] + slw3*VS[(l00+17)*91+ch];
    }
    SC[idx] = val;
  }
  __syncthreads();
  {
    float* ydst = g_y + pix*180;
    for (int nh=0; nh<6; nh++){
      float qs[15];
#pragma unroll
      for (int hd=0;hd<15;hd++) qs[hd] = QS[l*91 + nh*15 + hd];
      u64 q2[8];
#pragma unroll
      for (int p=0;p<7;p++) q2[p] = pk2(qs[2*p], qs[2*p+1]);
      q2[7] = pk2(qs[14], 0.f);
      const float* vp = SC + (nh<<10);
      const float* rpbrow = g_rpb + ((size_t)((nh<<8) + l))*64;
      u64 xs2[8];
#pragma unroll
      for (int p=0;p<8;p++) xs2[p]=0ull;
      for (int m0=0;m0<64;m0+=4){
        float4 rb = *(const float4*)(rpbrow + m0);
        float rbv[4] = {rb.x, rb.y, rb.z, rb.w};
#pragma unroll
        for (int t=0;t<4;t++){
          const ulonglong2* vpp = (const ulonglong2*)(vp + ((m0+t)<<4));
          ulonglong2 wA = vpp[0], wB = vpp[1], wC = vpp[2], wD = vpp[3];
          u64 d2 = fmul2(q2[0], wA.x);
          d2 = ffma2(q2[1], wA.y, d2);
          d2 = ffma2(q2[2], wB.x, d2);
          d2 = ffma2(q2[3], wB.y, d2);
          d2 = ffma2(q2[4], wC.x, d2);
          d2 = ffma2(q2[5], wC.y, d2);
          d2 = ffma2(q2[6], wD.x, d2);
          d2 = ffma2(q2[7], wD.y, d2);
          float lo,hi; up2(d2, lo, hi);
          u64 s2 = dup2((lo+hi)*(1.f/15.f) + rbv[t]);
          xs2[0] = ffma2(s2, wA.x, xs2[0]);
          xs2[1] = ffma2(s2, wA.y, xs2[1]);
          xs2[2] = ffma2(s2, wB.x, xs2[2]);
          xs2[3] = ffma2(s2, wB.y, xs2[3]);
          xs2[4] = ffma2(s2, wC.x, xs2[4]);
          xs2[5] = ffma2(s2, wC.y, xs2[5]);
          xs2[6] = ffma2(s2, wD.x, xs2[6]);
          xs2[7] = ffma2(s2, wD.y, xs2[7]);
        }
      }
#pragma unroll
      for (int p=0;p<7;p++){
        float lo,hi; up2(xs2[p], lo, hi);
        ydst[nh*15+2*p] = lo; ydst[nh*15+2*p+1] = hi;
      }
      { float lo,hi; up2(xs2[7], lo, hi); ydst[nh*15+14] = lo; }
    }
  }
  u64 cm2[6][3];
  int cb=0, db=0;
  bool act = (tid < 225);
  if (act){
    cb = (tid/15)*6; db = (tid%15)*6;
#pragma unroll
    for (int i=0;i<6;i++)
#pragma unroll
      for (int t=0;t<3;t++) cm2[i][t]=0ull;
    for (int ll=0; ll<256; ll++){
      u64 qr[6];
#pragma unroll
      for (int i=0;i<6;i++) qr[i] = dup2(QS[ll*91+cb+i]);
      u64 vr[3];
#pragma unroll
      for (int t=0;t<3;t++) vr[t] = pk2(VS[ll*91+db+2*t], VS[ll*91+db+2*t+1]);
#pragma unroll
      for (int i=0;i<6;i++)
#pragma unroll
        for (int t=0;t<3;t++) cm2[i][t] = ffma2(qr[i], vr[t], cm2[i][t]);
    }
  }
  __syncthreads();
  if (act){
#pragma unroll
    for (int i=0;i<6;i++)
#pragma unroll
      for (int t=0;t<3;t++){
        float lo,hi; up2(cm2[i][t], lo, hi);
        SC[(db+2*t  )*92 + cb+i] = lo*(1.f/256.f);
        SC[(db+2*t+1)*92 + cb+i] = hi*(1.f/256.f);
      }
  }
  __syncthreads();
  {
    float* ydst = g_y + pix*180 + 90;
    for (int c0=0;c0<90;c0+=18){
      u64 s2[9];
#pragma unroll
      for (int t=0;t<9;t++) s2[t]=0ull;
      for (int d=0; d<90; d++){
        u64 v2 = dup2(VS[l*91+d]);
        const u64* cp = (const u64*)(SC + d*92 + c0);
#pragma unroll
        for (int t=0;t<9;t++) s2[t] = ffma2(v2, cp[t], s2[t]);
      }
#pragma unroll
      for (int t=0;t<9;t++){
        float lo,hi; up2(s2[t], lo, hi);
        ydst[c0+2*t] = lo; ydst[c0+2*t+1] = hi;
      }
    }
  }
}

// =============== T3: t_proj: out = x + RMSNorm(g_y@pjw + pb)*nw ===============
__global__ void __launch_bounds__(256) t_proj(const float* __restrict__ x,
                                              const float* __restrict__ pb,
                                              const float* __restrict__ nw,
                                              float* __restrict__ out){
  extern __shared__ __align__(16) char smc[];
  __shared__ float scl[128];
  __nv_bfloat16* Ab = (__nv_bfloat16*)smc;
  __nv_bfloat16* Bs = Ab + 6*9216;
  int tid = threadIdx.x; int lane = tid&31, wid = tid>>5;
  int wm = wid&3, wn = wid>>2;
  int r0 = blockIdx.x*128; int bb = r0>>16; int p0 = r0&65535;

  for (int idx=tid; idx<128*192; idx+=256){
    int px = idx/192, cc = idx - px*192;
    float v = (cc<180) ? g_y[(size_t)(r0+px)*180 + cc] : 0.f;
    __nv_bfloat16 h,l; cvhl(v,h,l);
    int t = cc>>6, k = cc&63;
    Ab[t*9216 + px*72 + k]     = h;
    Ab[(t+3)*9216 + px*72 + k] = l;
  }
  float c[2][12][4];
#pragma unroll
  for (int mt=0;mt<2;mt++)
#pragma unroll
    for (int nt=0;nt<12;nt++)
#pragma unroll
      for (int e=0;e<4;e++) c[mt][nt][e]=0.f;

  for (int i=0;i<6;i++){
    __syncthreads();
    const uint4* src = (const uint4*)(g_pk_pj + i*13824);
    uint4* dst = (uint4*)Bs;
    for (int t=tid;t<1728;t+=256) dst[t]=src[t];
    __syncthreads();
    if (i<3){
      mma_pass(Ab + i*9216,     Bs, 72, 72, 4, c, lane, wm, wn);
      mma_pass(Ab + (3+i)*9216, Bs, 72, 72, 4, c, lane, wm, wn);
    } else {
      mma_pass(Ab + (i-3)*9216, Bs, 72, 72, 4, c, lane, wm, wn);
    }
  }
  __syncthreads();
  float* stash = (float*)smc;
#pragma unroll
  for (int mt=0;mt<2;mt++){
    int r1 = wm*32 + mt*16 + (lane>>2);
#pragma unroll
    for (int nt=0;nt<12;nt++){
      int n0 = wn*96 + nt*8 + (lane&3)*2;
      if (n0 < 180){
        float b0=__ldg(pb+n0), b1=__ldg(pb+n0+1);
        stash[r1*181+n0]       = c[mt][nt][0]+b0;
        stash[r1*181+n0+1]     = c[mt][nt][1]+b1;
        stash[(r1+8)*181+n0]   = c[mt][nt][2]+b0;
        stash[(r1+8)*181+n0+1] = c[mt][nt][3]+b1;
      }
    }
  }
  __syncthreads();
  if (tid < 128){
    const float* row = stash + tid*181;
    float s = 0.f;
    for (int cc=0; cc<180; cc++){ float v = row[cc]; s += v*v; }
    scl[tid] = rsqrtf(s*(1.f/180.f) + 1.1920929e-07f);
  }
  __syncthreads();
  {
    int px = tid&127;
    int half = tid>>7;
    float sc = scl[px];
    for (int ci=0; ci<90; ci++){
      int co = 2*ci + half;
      size_t a = ((size_t)(bb*180+co))*NPIX + p0 + px;
      out[a] = x[a] + stash[px*181+co]*sc*__ldg(nw+co);
    }
  }
}

// =============== launch ===============
extern "C" void kernel_launch(void* const* d_in, const int* in_sizes, int n_in,
                              void* d_out, int out_size){
  const float* x     = (const float*)d_in[0];
  const float* w1    = (const float*)d_in[1];
  const float* b1    = (const float*)d_in[2];
  const float* w2    = (const float*)d_in[3];
  const float* b2    = (const float*)d_in[4];
  const float* w3    = (const float*)d_in[5];
  const float* b3    = (const float*)d_in[6];
  const float* lw    = (const float*)d_in[7];
  const float* lb    = (const float*)d_in[8];
  const float* sl_w  = (const float*)d_in[9];
  const float* sl_b  = (const float*)d_in[10];
  const float* ppw   = (const float*)d_in[11];
  const float* ppb   = (const float*)d_in[12];
  const float* ln1w  = (const float*)d_in[13];
  const float* ln1b  = (const float*)d_in[14];
  const float* l1w   = (const float*)d_in[15];
  const float* l1b   = (const float*)d_in[16];
  const float* ln2w  = (const float*)d_in[17];
  const float* ln2b  = (const float*)d_in[18];
  const float* l2w   = (const float*)d_in[19];
  const float* l2b   = (const float*)d_in[20];
  const float* ln3w  = (const float*)d_in[21];
  const float* ln3b  = (const float*)d_in[22];
  const float* l3w   = (const float*)d_in[23];
  const float* l3b   = (const float*)d_in[24];
  const float* pjw   = (const float*)d_in[25];
  const float* pjb   = (const float*)d_in[26];
  const float* nrmw  = (const float*)d_in[27];
  float* out = (float*)d_out;

  const int SM_K2  = (11988 + 11664) * 4;        // 94608 B
  const int SM_K4  = (2*256*91 + 8280) * 4;      // 219488 B
  const int SM_TL  = (6*9216 + 13824) * 2;       // 138240 B
  const int SM_TH  = 92672;                      // stash dominates
  cudaFuncSetAttribute(k_conv3, cudaFuncAttributeMaxDynamicSharedMemorySize, SM_K2);
  cudaFuncSetAttribute(k_attn,  cudaFuncAttributeMaxDynamicSharedMemorySize, SM_K4);
  cudaFuncSetAttribute(t_lin,   cudaFuncAttributeMaxDynamicSharedMemorySize, SM_TL);
  cudaFuncSetAttribute(t_h3,    cudaFuncAttributeMaxDynamicSharedMemorySize, SM_TH);
  cudaFuncSetAttribute(t_proj,  cudaFuncAttributeMaxDynamicSharedMemorySize, SM_TL);

  k_pack180<<<(6*13824+255)/256,256>>>(lw, 0);
  k_pack180<<<(6*13824+255)/256,256>>>(pjw, 1);
  k_pack36<<<(2*10752+255)/256,256>>>(w3);
  k_pos<<<4,256>>>(ppw, ppb, ln1w, ln1b, l1w, l1b, ln2w, ln2b, l2w, l2b, ln3w, ln3b, l3w, l3b);
  k_rpb<<<384,256>>>();
  k_dfe1<<<TOTPIX/256,256>>>(x, w1, b1);
  k_conv3<<<dim3(16,16,4),256,SM_K2>>>(w2, b2);
  t_lin<<<TOTPIX/128,256,SM_TL>>>(x, lb);
  t_h3<<<TOTPIX/128,256,SM_TH>>>(b3);
  k_attn<<<NWIN,256,SM_K4>>>(sl_w, sl_b);
  t_proj<<<TOTPIX/128,256,SM_TL>>>(x, pjb, nrmw, out);
}

// round 6
// speedup vs baseline: 1.0996x; 1.0996x over previous
#include <cuda_runtime.h>
#include <cuda_bf16.h>
#include <math.h>
#include <stdint.h>

#define NBATCH 4
#define NCH    180
#define IMG    256
#define NPIX   (IMG*IMG)            // 65536
#define TOTPIX (NBATCH*NPIX)        // 262144
#define MIDC   36
#define NWIN   1024

// ---- scratch (device globals; no allocation allowed) ----
__device__ float g_h1[(size_t)TOTPIX*MIDC];
__device__ float g_h2[(size_t)TOTPIX*MIDC];
__device__ float g_qv[(size_t)TOTPIX*NCH];
__device__ float g_y [(size_t)TOTPIX*NCH];
__device__ float g_pos[961*6];
__device__ float g_rpb[6*256*64];
// packed bf16 weights, transposed [n][k] padded tiles
__device__ __align__(16) __nv_bfloat16 g_pk_lw[6*13824];  // [192][72] x (Bh0..2,Bl0..2)
__device__ __align__(16) __nv_bfloat16 g_pk_pj[6*13824];
__device__ __align__(16) __nv_bfloat16 g_pk_w3[2*10752];  // [192][56] x (hi,lo)

typedef unsigned long long u64;

__device__ __forceinline__ u64 pk2(float lo, float hi){
  u64 r; asm("mov.b64 %0,{%1,%2};" : "=l"(r) : "f"(lo), "f"(hi)); return r;
}
__device__ __forceinline__ u64 dup2(float v){ return pk2(v, v); }
__device__ __forceinline__ void up2(u64 v, float& lo, float& hi){
  asm("mov.b64 {%0,%1},%2;" : "=f"(lo), "=f"(hi) : "l"(v));
}
__device__ __forceinline__ u64 ffma2(u64 a, u64 b, u64 c){
  u64 d; asm("fma.rn.f32x2 %0,%1,%2,%3;" : "=l"(d) : "l"(a), "l"(b), "l"(c)); return d;
}
__device__ __forceinline__ u64 fmul2(u64 a, u64 b){
  u64 d; asm("mul.rn.f32x2 %0,%1,%2;" : "=l"(d) : "l"(a), "l"(b)); return d;
}
__device__ __forceinline__ float lrelu(float v){ return v >= 0.f ? v : 0.2f*v; }

__device__ __forceinline__ void cvhl(float v, __nv_bfloat16& h, __nv_bfloat16& l){
  h = __float2bfloat16(v);
  l = __float2bfloat16(v - __bfloat162float(h));
}

// ---- portable tensor-core primitives ----
#define MMA16816(c, a, b0, b1) \
  asm volatile("mma.sync.aligned.m16n8k16.row.col.f32.bf16.bf16.f32 " \
    "{%0,%1,%2,%3}, {%4,%5,%6,%7}, {%8,%9}, {%0,%1,%2,%3};" \
    : "+f"((c)[0]), "+f"((c)[1]), "+f"((c)[2]), "+f"((c)[3]) \
    : "r"((a)[0]), "r"((a)[1]), "r"((a)[2]), "r"((a)[3]), "r"(b0), "r"(b1))

__device__ __forceinline__ void ldsm_x4(uint32_t r[4], uint32_t saddr){
  asm volatile("ldmatrix.sync.aligned.m8n8.x4.shared.b16 {%0,%1,%2,%3}, [%4];"
    : "=r"(r[0]),"=r"(r[1]),"=r"(r[2]),"=r"(r[3]) : "r"(saddr));
}
__device__ __forceinline__ void cpa16(uint32_t d, const void* s){
  asm volatile("cp.async.cg.shared.global [%0], [%1], 16;" :: "r"(d), "l"(s));
}
#define CP_COMMIT() asm volatile("cp.async.commit_group;" ::: "memory")
#define CP_WAIT(n)  asm volatile("cp.async.wait_group %0;" :: "n"(n) : "memory")

// one pass: A[128][K]@smem x B[192][K]^T@smem -> c (warp tile 32x96), strides in bf16 elems
template<int SA, int SB, int NKS>
__device__ __forceinline__ void mma_pass(uint32_t aBase, uint32_t bBase,
                                         float c[2][12][4], int lane, int wm, int wn){
  uint32_t aoff[2], boff[6];
  int ar = (lane&7) + ((lane&8)?8:0);
  int ak = (lane&16)?8:0;
#pragma unroll
  for (int mt=0;mt<2;mt++) aoff[mt] = aBase + (uint32_t)(((wm*32+mt*16+ar)*SA + ak)*2);
  int br = (lane&7) + ((lane&16)?8:0);
  int bk = (lane&8)?8:0;
#pragma unroll
  for (int p=0;p<6;p++) boff[p] = bBase + (uint32_t)(((wn*96+p*16+br)*SB + bk)*2);
#pragma unroll
  for (int ks=0;ks<NKS;ks++){
    uint32_t a0[4], a1[4];
    ldsm_x4(a0, aoff[0] + ks*32);
    ldsm_x4(a1, aoff[1] + ks*32);
#pragma unroll
    for (int p=0;p<6;p++){
      uint32_t b[4];
      ldsm_x4(b, boff[p] + ks*32);
      MMA16816(c[0][2*p],   a0, b[0], b[1]);
      MMA16816(c[1][2*p],   a1, b[0], b[1]);
      MMA16816(c[0][2*p+1], a0, b[2], b[3]);
      MMA16816(c[1][2*p+1], a1, b[2], b[3]);
    }
  }
}

// =============== pack kernels ===============
__global__ void k_pack180(const float* __restrict__ W, int which){
  __nv_bfloat16* dst = which ? g_pk_pj : g_pk_lw;
  int idx = blockIdx.x*256 + threadIdx.x;
  if (idx >= 6*13824) return;
  int cc = idx/13824, r = idx - cc*13824, n = r/72, k = r - n*72;
  int half = cc/3, kc = cc - half*3;
  int kk = kc*64 + k;
  float v = (n<180 && k<64 && kk<180) ? W[kk*180+n] : 0.f;
  __nv_bfloat16 h, l; cvhl(v, h, l);
  dst[idx] = half ? l : h;
}
__global__ void k_pack36(const float* __restrict__ W){
  int idx = blockIdx.x*256 + threadIdx.x;
  if (idx >= 2*10752) return;
  int cc = idx/10752, r = idx - cc*10752, n = r/56, k = r - n*56;
  float v = (n<180 && k<36) ? W[k*180+n] : 0.f;
  __nv_bfloat16 h, l; cvhl(v, h, l);
  g_pk_w3[idx] = cc ? l : h;
}

// =============== T1: t_lin: g_y = x @ lw + lb ===============
__global__ void __launch_bounds__(256) t_lin(const float* __restrict__ x,
                                             const float* __restrict__ lb){
  extern __shared__ __align__(16) char smc[];
  __nv_bfloat16* Ab = (__nv_bfloat16*)smc;              // 6*9216 bf16
  const uint32_t O_B0 = 6*9216*2, O_B1 = O_B0 + 13824*2;  // bytes
  uint32_t sbase = (uint32_t)__cvta_generic_to_shared(smc);
  int tid = threadIdx.x; int lane = tid&31, wid = tid>>5;
  int wm = wid&3, wn = wid>>2;
  int r0 = blockIdx.x*128; int bb = r0>>16; int p0 = r0&65535;

  // prefetch B chunk 0
  for (int t=tid; t<1728; t+=256)
    cpa16(sbase + O_B0 + t*16, (const char*)(g_pk_lw) + t*16);
  CP_COMMIT();

  // A prologue
  for (int idx=tid; idx<192*128; idx+=256){
    int c = idx>>7, px = idx&127;
    float v = (c<180) ? x[((size_t)(bb*180+c))*NPIX + p0+px] : 0.f;
    __nv_bfloat16 h,l; cvhl(v,h,l);
    int t = c>>6, k = c&63;
    Ab[t*9216 + px*72 + k]     = h;
    Ab[(t+3)*9216 + px*72 + k] = l;
  }
  float c[2][12][4];
#pragma unroll
  for (int mt=0;mt<2;mt++)
#pragma unroll
    for (int nt=0;nt<12;nt++)
#pragma unroll
      for (int e=0;e<4;e++) c[mt][nt][e]=0.f;

  for (int i=0;i<6;i++){
    uint32_t bo = (i&1) ? O_B1 : O_B0;
    if (i<5){
      uint32_t bn = ((i+1)&1) ? O_B1 : O_B0;
      for (int t=tid; t<1728; t+=256)
        cpa16(sbase + bn + t*16, (const char*)(g_pk_lw + (i+1)*13824) + t*16);
      CP_COMMIT();
      CP_WAIT(1);
    } else {
      CP_WAIT(0);
    }
    __syncthreads();
    if (i<3){
      mma_pass<72,72,4>(sbase + (uint32_t)(i*9216*2),     sbase + bo, c, lane, wm, wn);
      mma_pass<72,72,4>(sbase + (uint32_t)((3+i)*9216*2), sbase + bo, c, lane, wm, wn);
    } else {
      mma_pass<72,72,4>(sbase + (uint32_t)((i-3)*9216*2), sbase + bo, c, lane, wm, wn);
    }
    __syncthreads();
  }
  float* stash = (float*)smc;  // 128*181*4 = 92672 <= A region
#pragma unroll
  for (int mt=0;mt<2;mt++){
    int r1 = wm*32 + mt*16 + (lane>>2);
#pragma unroll
    for (int nt=0;nt<12;nt++){
      int n0 = wn*96 + nt*8 + (lane&3)*2;
      if (n0 < 180){
        float bl0=__ldg(lb+n0), bl1=__ldg(lb+n0+1);
        stash[r1*181+n0]       = c[mt][nt][0]+bl0;
        stash[r1*181+n0+1]     = c[mt][nt][1]+bl1;
        stash[(r1+8)*181+n0]   = c[mt][nt][2]+bl0;
        stash[(r1+8)*181+n0+1] = c[mt][nt][3]+bl1;
      }
    }
  }
  __syncthreads();
  {
    int f = tid;
    int px = f/180, co = f - px*180;
    for (; f < 128*180; f += 256){
      g_y[(size_t)r0*180 + f] = stash[px*181+co];
      co += 256; if (co >= 180){ co -= 180; px++; if (co >= 180){ co -= 180; px++; } }
    }
  }
}

// =============== K0a: position-bias MLP ===============
__device__ __forceinline__ void ln_relu11(const float* in, const float* w, const float* b, float* out){
  float m = 0.f;
#pragma unroll
  for (int j=0;j<11;j++) m += in[j];
  m *= (1.f/11.f);
  float var = 0.f;
#pragma unroll
  for (int j=0;j<11;j++){ float d = in[j]-m; var += d*d; }
  var *= (1.f/11.f);
  float inv = rsqrtf(var + 1e-5f);
#pragma unroll
  for (int j=0;j<11;j++) out[j] = fmaxf((in[j]-m)*inv*w[j] + b[j], 0.f);
}

__global__ void k_pos(const float* __restrict__ pw, const float* __restrict__ pb,
                      const float* __restrict__ ln1w, const float* __restrict__ ln1b,
                      const float* __restrict__ w1,  const float* __restrict__ b1,
                      const float* __restrict__ ln2w, const float* __restrict__ ln2b,
                      const float* __restrict__ w2,  const float* __restrict__ b2,
                      const float* __restrict__ ln3w, const float* __restrict__ ln3b,
                      const float* __restrict__ w3,  const float* __restrict__ b3){
  int n = blockIdx.x*blockDim.x + threadIdx.x;
  if (n >= 961) return;
  float i0 = (float)(n/31) - 15.f;
  float i1 = (float)(n%31) - 15.f;
  float p[11], t[11];
#pragma unroll
  for (int j=0;j<11;j++) p[j] = i0*pw[j] + i1*pw[11+j] + pb[j];
  ln_relu11(p, ln1w, ln1b, t);
#pragma unroll
  for (int k=0;k<11;k++){ float s=b1[k];
#pragma unroll
    for (int j=0;j<11;j++) s += t[j]*w1[j*11+k]; p[k]=s; }
  ln_relu11(p, ln2w, ln2b, t);
#pragma unroll
  for (int k=0;k<11;k++){ float s=b2[k];
#pragma unroll
    for (int j=0;j<11;j++) s += t[j]*w2[j*11+k]; p[k]=s; }
  ln_relu11(p, ln3w, ln3b, t);
#pragma unroll
  for (int k=0;k<6;k++){ float s=b3[k];
#pragma unroll
    for (int j=0;j<11;j++) s += t[j]*w3[j*6+k];
    g_pos[n*6+k] = s; }
}

// =============== K0b: rpb ===============
__global__ void k_rpb(){
  int idx = blockIdx.x*blockDim.x + threadIdx.x;
  if (idx >= 6*256*64) return;
  int nh = idx/16384;
  int r  = idx - nh*16384;
  int l  = r>>6;
  int m  = r&63;
  int rl = l>>4, cl = l&15;
  int mh = m>>3, mw = m&7;
  float s = 0.f;
#pragma unroll
  for (int rh=0;rh<2;rh++)
#pragma unroll
    for (int rw=0;rw<2;rw++){
      int r2 = mh*2+rh, c2 = mw*2+rw;
      int k = (rl-r2+15)*31 + (cl-c2+15);
      s += g_pos[k*6+nh];
    }
  g_rpb[idx] = 0.25f*s;
}

// =============== K1: h1 = lrelu(x @ w1 + b1) ===============
__global__ void __launch_bounds__(256) k_dfe1(const float* __restrict__ x,
                                              const float* __restrict__ w1,
                                              const float* __restrict__ b1){
  __shared__ __align__(16) float ws[180*36];
  int tid = threadIdx.x;
  for (int t=tid;t<180*36;t+=256) ws[t]=w1[t];
  __syncthreads();
  int r = blockIdx.x*256 + tid;
  int b = r>>16; int p = r&65535;
  const float* xp = x + (size_t)b*NCH*NPIX + p;
  u64 acc2[18];
#pragma unroll
  for (int q=0;q<18;q++) acc2[q] = pk2(b1[2*q], b1[2*q+1]);
  for (int ci=0;ci<180;ci++){
    u64 v2 = dup2(xp[(size_t)ci*NPIX]);
    const ulonglong2* wr = (const ulonglong2*)(ws + ci*36);
#pragma unroll
    for (int q=0;q<9;q++){
      ulonglong2 w = wr[q];
      acc2[2*q]   = ffma2(v2, w.x, acc2[2*q]);
      acc2[2*q+1] = ffma2(v2, w.y, acc2[2*q+1]);
    }
  }
  float2* dst = (float2*)(g_h1 + (size_t)r*36);
#pragma unroll
  for (int q=0;q<18;q++){
    float lo,hi; up2(acc2[q], lo, hi);
    dst[q] = make_float2(lrelu(lo), lrelu(hi));
  }
}

// =============== K2: h2 = lrelu(conv3x3(h1)) ===============
__global__ void __launch_bounds__(256) k_conv3(const float* __restrict__ w2,
                                               const float* __restrict__ b2){
  extern __shared__ float sm2[];
  float* ins = sm2;             // 18*18*37
  float* wsh = sm2 + 11988;     // 9*36*36
  int tid = threadIdx.x;
  int b = blockIdx.z; int hy0 = blockIdx.y*16, wx0 = blockIdx.x*16;
  for (int t=tid;t<18*18*36;t+=256){
    int ci = t%36; int rc = t/36; int col = rc%18; int row = rc/18;
    int gh = hy0+row-1, gw = wx0+col-1;
    float v = 0.f;
    if (gh>=0 && gh<IMG && gw>=0 && gw<IMG)
      v = g_h1[((size_t)(b*IMG+gh)*IMG+gw)*36 + ci];
    ins[(row*18+col)*37+ci] = v;
  }
  for (int t=tid;t<9*36*36;t+=256) wsh[t] = w2[t];
  __syncthreads();
  int tx = tid&15, ty = tid>>4;
  float acc[36];
#pragma unroll
  for (int co=0;co<36;co++) acc[co] = b2[co];
  for (int dy=0;dy<3;dy++)
    for (int dx=0;dx<3;dx++){
      const float* wp = wsh + (dy*3+dx)*36*36;
      const float* ip = ins + ((ty+dy)*18 + tx+dx)*37;
      for (int ci=0;ci<36;ci++){
        float v = ip[ci];
        const float* wr = wp + ci*36;
#pragma unroll
        for (int co=0;co<36;co++) acc[co] += v*wr[co];
      }
    }
  size_t o = ((size_t)(b*IMG+hy0+ty)*IMG + wx0+tx)*36;
  float4* dst = (float4*)(g_h2 + o);
#pragma unroll
  for (int q=0;q<9;q++){
    float4 r; r.x=lrelu(acc[q*4]); r.y=lrelu(acc[q*4+1]); r.z=lrelu(acc[q*4+2]); r.w=lrelu(acc[q*4+3]);
    dst[q]=r;
  }
}

// =============== T2: t_h3: g_qv = (h2 @ w3 + b3) * g_y ===============
__global__ void __launch_bounds__(256) t_h3(const float* __restrict__ b3){
  extern __shared__ __align__(16) char smc[];
  __nv_bfloat16* Ab = (__nv_bfloat16*)smc;    // hi @0, lo @7168 elems
  const uint32_t O_B = 14336*2;               // B hi @0, lo @10752 elems after
  uint32_t sbase = (uint32_t)__cvta_generic_to_shared(smc);
  int tid = threadIdx.x; int lane = tid&31, wid = tid>>5;
  int wm = wid&3, wn = wid>>2;
  int r0 = blockIdx.x*128;

  for (int t=tid; t<2688; t+=256)
    cpa16(sbase + O_B + t*16, (const char*)(g_pk_w3) + t*16);
  CP_COMMIT();

  for (int idx=tid; idx<128*48; idx+=256){
    int px = idx/48, cc = idx - px*48;
    float v = (cc<36) ? g_h2[(size_t)(r0+px)*36 + cc] : 0.f;
    __nv_bfloat16 h,l; cvhl(v,h,l);
    Ab[px*56 + cc]        = h;
    Ab[7168 + px*56 + cc] = l;
  }
  CP_WAIT(0);
  __syncthreads();
  float c[2][12][4];
#pragma unroll
  for (int mt=0;mt<2;mt++)
#pragma unroll
    for (int nt=0;nt<12;nt++)
#pragma unroll
      for (int e=0;e<4;e++) c[mt][nt][e]=0.f;

  mma_pass<56,56,3>(sbase,           sbase + O_B,           c, lane, wm, wn); // Ah,Bh
  mma_pass<56,56,3>(sbase + 7168*2,  sbase + O_B,           c, lane, wm, wn); // Al,Bh
  mma_pass<56,56,3>(sbase,           sbase + O_B + 10752*2, c, lane, wm, wn); // Ah,Bl
  __syncthreads();
  float* stash = (float*)smc;
#pragma unroll
  for (int mt=0;mt<2;mt++){
    int r1 = wm*32 + mt*16 + (lane>>2);
#pragma unroll
    for (int nt=0;nt<12;nt++){
      int n0 = wn*96 + nt*8 + (lane&3)*2;
      if (n0 < 180){
        float b30=__ldg(b3+n0), b31=__ldg(b3+n0+1);
        stash[r1*181+n0]       = c[mt][nt][0]+b30;
        stash[r1*181+n0+1]     = c[mt][nt][1]+b31;
        stash[(r1+8)*181+n0]   = c[mt][nt][2]+b30;
        stash[(r1+8)*181+n0+1] = c[mt][nt][3]+b31;
      }
    }
  }
  __syncthreads();
  {
    int f = tid;
    int px = f/180, co = f - px*180;
    for (; f < 128*180; f += 256){
      g_qv[(size_t)r0*180 + f] = stash[px*181+co] * g_y[(size_t)r0*180 + f];
      co += 256; if (co >= 180){ co -= 180; px++; if (co >= 180){ co -= 180; px++; } }
    }
  }
}

// =============== K4: per-window attention ===============
__global__ void __launch_bounds__(256) k_attn(const float* __restrict__ sl_w,
                                              const float* __restrict__ sl_b){
  extern __shared__ float sm4[];
  float* QS = sm4;
  float* VS = sm4 + 256*91;
  float* SC = sm4 + 2*256*91;
  int tid = threadIdx.x;
  int bw = blockIdx.x;
  int b = bw>>8, wy = (bw>>4)&15, wx = bw&15;
  int l = tid;
  int gh = wy*16 + (l>>4), gw = wx*16 + (l&15);
  size_t pix = ((size_t)(b*IMG+gh))*IMG + gw;
  {
    const float4* src = (const float4*)(g_qv + pix*180);
#pragma unroll
    for (int k=0;k<45;k++){
      float4 v4 = src[k];
      int c0 = k*4;
      float vals[4] = {v4.x,v4.y,v4.z,v4.w};
#pragma unroll
      for (int e=0;e<4;e++){
        int c = c0+e;
        if (c < 90) QS[l*91+c] = vals[e];
        else        VS[l*91+(c-90)] = vals[e];
      }
    }
  }
  __syncthreads();
  float slw0=sl_w[0], slw1=sl_w[1], slw2=sl_w[2], slw3=sl_w[3], slb=sl_b[0];
  for (int idx=tid; idx<6144; idx+=256){
    int nh = idx>>10; int r = idx & 1023; int m = r>>4; int hd = r&15;
    float val = 0.f;
    if (hd < 15){
      int mh = m>>3, mw = m&7; int ch = nh*15+hd;
      int l00 = (mh*2)*16 + mw*2;
      val = slb + slw0*VS[l00*91+ch]      + slw1*VS[(l00+1)*91+ch]
                + slw2*VS[(l00+16)*91+ch] + slw3*VS[(l00+17)*91+ch];
    }
    SC[idx] = val;
  }
  __syncthreads();
  {
    float* ydst = g_y + pix*180;
    for (int nh=0; nh<6; nh++){
      float qs[15];
#pragma unroll
      for (int hd=0;hd<15;hd++) qs[hd] = QS[l*91 + nh*15 + hd];
      u64 q2[8];
#pragma unroll
      for (int p=0;p<7;p++) q2[p] = pk2(qs[2*p], qs[2*p+1]);
      q2[7] = pk2(qs[14], 0.f);
      const float* vp = SC + (nh<<10);
      const float* rpbrow = g_rpb + ((size_t)((nh<<8) + l))*64;
      u64 xs2[8];
#pragma unroll
      for (int p=0;p<8;p++) xs2[p]=0ull;
      for (int m0=0;m0<64;m0+=4){
        float4 rb = *(const float4*)(rpbrow + m0);
        float rbv[4] = {rb.x, rb.y, rb.z, rb.w};
#pragma unroll
        for (int t=0;t<4;t++){
          const ulonglong2* vpp = (const ulonglong2*)(vp + ((m0+t)<<4));
          ulonglong2 wA = vpp[0], wB = vpp[1], wC = vpp[2], wD = vpp[3];
          u64 d2 = fmul2(q2[0], wA.x);
          d2 = ffma2(q2[1], wA.y, d2);
          d2 = ffma2(q2[2], wB.x, d2);
          d2 = ffma2(q2[3], wB.y, d2);
          d2 = ffma2(q2[4], wC.x, d2);
          d2 = ffma2(q2[5], wC.y, d2);
          d2 = ffma2(q2[6], wD.x, d2);
          d2 = ffma2(q2[7], wD.y, d2);
          float lo,hi; up2(d2, lo, hi);
          u64 s2 = dup2((lo+hi)*(1.f/15.f) + rbv[t]);
          xs2[0] = ffma2(s2, wA.x, xs2[0]);
          xs2[1] = ffma2(s2, wA.y, xs2[1]);
          xs2[2] = ffma2(s2, wB.x, xs2[2]);
          xs2[3] = ffma2(s2, wB.y, xs2[3]);
          xs2[4] = ffma2(s2, wC.x, xs2[4]);
          xs2[5] = ffma2(s2, wC.y, xs2[5]);
          xs2[6] = ffma2(s2, wD.x, xs2[6]);
          xs2[7] = ffma2(s2, wD.y, xs2[7]);
        }
      }
#pragma unroll
      for (int p=0;p<7;p++){
        float lo,hi; up2(xs2[p], lo, hi);
        ydst[nh*15+2*p] = lo; ydst[nh*15+2*p+1] = hi;
      }
      { float lo,hi; up2(xs2[7], lo, hi); ydst[nh*15+14] = lo; }
    }
  }
  u64 cm2[6][3];
  int cb=0, db=0;
  bool act = (tid < 225);
  if (act){
    cb = (tid/15)*6; db = (tid%15)*6;
#pragma unroll
    for (int i=0;i<6;i++)
#pragma unroll
      for (int t=0;t<3;t++) cm2[i][t]=0ull;
    for (int ll=0; ll<256; ll++){
      u64 qr[6];
#pragma unroll
      for (int i=0;i<6;i++) qr[i] = dup2(QS[ll*91+cb+i]);
      u64 vr[3];
#pragma unroll
      for (int t=0;t<3;t++) vr[t] = pk2(VS[ll*91+db+2*t], VS[ll*91+db+2*t+1]);
#pragma unroll
      for (int i=0;i<6;i++)
#pragma unroll
        for (int t=0;t<3;t++) cm2[i][t] = ffma2(qr[i], vr[t], cm2[i][t]);
    }
  }
  __syncthreads();
  if (act){
#pragma unroll
    for (int i=0;i<6;i++)
#pragma unroll
      for (int t=0;t<3;t++){
        float lo,hi; up2(cm2[i][t], lo, hi);
        SC[(db+2*t  )*92 + cb+i] = lo*(1.f/256.f);
        SC[(db+2*t+1)*92 + cb+i] = hi*(1.f/256.f);
      }
  }
  __syncthreads();
  {
    float* ydst = g_y + pix*180 + 90;
    for (int c0=0;c0<90;c0+=18){
      u64 s2[9];
#pragma unroll
      for (int t=0;t<9;t++) s2[t]=0ull;
      for (int d=0; d<90; d++){
        u64 v2 = dup2(VS[l*91+d]);
        const u64* cp = (const u64*)(SC + d*92 + c0);
#pragma unroll
        for (int t=0;t<9;t++) s2[t] = ffma2(v2, cp[t], s2[t]);
      }
#pragma unroll
      for (int t=0;t<9;t++){
        float lo,hi; up2(s2[t], lo, hi);
        ydst[c0+2*t] = lo; ydst[c0+2*t+1] = hi;
      }
    }
  }
}

// =============== T3: t_proj: out = x + RMSNorm(g_y@pjw + pb)*nw ===============
__global__ void __launch_bounds__(256) t_proj(const float* __restrict__ x,
                                              const float* __restrict__ pb,
                                              const float* __restrict__ nw,
                                              float* __restrict__ out){
  extern __shared__ __align__(16) char smc[];
  __shared__ float scl[128];
  __nv_bfloat16* Ab = (__nv_bfloat16*)smc;
  const uint32_t O_B0 = 6*9216*2, O_B1 = O_B0 + 13824*2;
  uint32_t sbase = (uint32_t)__cvta_generic_to_shared(smc);
  int tid = threadIdx.x; int lane = tid&31, wid = tid>>5;
  int wm = wid&3, wn = wid>>2;
  int r0 = blockIdx.x*128; int bb = r0>>16; int p0 = r0&65535;

  for (int t=tid; t<1728; t+=256)
    cpa16(sbase + O_B0 + t*16, (const char*)(g_pk_pj) + t*16);
  CP_COMMIT();

  for (int idx=tid; idx<128*192; idx+=256){
    int px = idx/192, cc = idx - px*192;
    float v = (cc<180) ? g_y[(size_t)(r0+px)*180 + cc] : 0.f;
    __nv_bfloat16 h,l; cvhl(v,h,l);
    int t = cc>>6, k = cc&63;
    Ab[t*9216 + px*72 + k]     = h;
    Ab[(t+3)*9216 + px*72 + k] = l;
  }
  float c[2][12][4];
#pragma unroll
  for (int mt=0;mt<2;mt++)
#pragma unroll
    for (int nt=0;nt<12;nt++)
#pragma unroll
      for (int e=0;e<4;e++) c[mt][nt][e]=0.f;

  for (int i=0;i<6;i++){
    uint32_t bo = (i&1) ? O_B1 : O_B0;
    if (i<5){
      uint32_t bn = ((i+1)&1) ? O_B1 : O_B0;
      for (int t=tid; t<1728; t+=256)
        cpa16(sbase + bn + t*16, (const char*)(g_pk_pj + (i+1)*13824) + t*16);
      CP_COMMIT();
      CP_WAIT(1);
    } else {
      CP_WAIT(0);
    }
    __syncthreads();
    if (i<3){
      mma_pass<72,72,4>(sbase + (uint32_t)(i*9216*2),     sbase + bo, c, lane, wm, wn);
      mma_pass<72,72,4>(sbase + (uint32_t)((3+i)*9216*2), sbase + bo, c, lane, wm, wn);
    } else {
      mma_pass<72,72,4>(sbase + (uint32_t)((i-3)*9216*2), sbase + bo, c, lane, wm, wn);
    }
    __syncthreads();
  }
  float* stash = (float*)smc;
#pragma unroll
  for (int mt=0;mt<2;mt++){
    int r1 = wm*32 + mt*16 + (lane>>2);
#pragma unroll
    for (int nt=0;nt<12;nt++){
      int n0 = wn*96 + nt*8 + (lane&3)*2;
      if (n0 < 180){
        float b0=__ldg(pb+n0), b1=__ldg(pb+n0+1);
        stash[r1*181+n0]       = c[mt][nt][0]+b0;
        stash[r1*181+n0+1]     = c[mt][nt][1]+b1;
        stash[(r1+8)*181+n0]   = c[mt][nt][2]+b0;
        stash[(r1+8)*181+n0+1] = c[mt][nt][3]+b1;
      }
    }
  }
  __syncthreads();
  if (tid < 128){
    const float* row = stash + tid*181;
    float s = 0.f;
    for (int cc=0; cc<180; cc++){ float v = row[cc]; s += v*v; }
    scl[tid] = rsqrtf(s*(1.f/180.f) + 1.1920929e-07f);
  }
  __syncthreads();
  {
    int px = tid&127;
    int half = tid>>7;
    float sc = scl[px];
    for (int ci=0; ci<90; ci++){
      int co = 2*ci + half;
      size_t a = ((size_t)(bb*180+co))*NPIX + p0 + px;
      out[a] = x[a] + stash[px*181+co]*sc*__ldg(nw+co);
    }
  }
}

// =============== launch ===============
extern "C" void kernel_launch(void* const* d_in, const int* in_sizes, int n_in,
                              void* d_out, int out_size){
  const float* x     = (const float*)d_in[0];
  const float* w1    = (const float*)d_in[1];
  const float* b1    = (const float*)d_in[2];
  const float* w2    = (const float*)d_in[3];
  const float* b2    = (const float*)d_in[4];
  const float* w3    = (const float*)d_in[5];
  const float* b3    = (const float*)d_in[6];
  const float* lw    = (const float*)d_in[7];
  const float* lb    = (const float*)d_in[8];
  const float* sl_w  = (const float*)d_in[9];
  const float* sl_b  = (const float*)d_in[10];
  const float* ppw   = (const float*)d_in[11];
  const float* ppb   = (const float*)d_in[12];
  const float* ln1w  = (const float*)d_in[13];
  const float* ln1b  = (const float*)d_in[14];
  const float* l1w   = (const float*)d_in[15];
  const float* l1b   = (const float*)d_in[16];
  const float* ln2w  = (const float*)d_in[17];
  const float* ln2b  = (const float*)d_in[18];
  const float* l2w   = (const float*)d_in[19];
  const float* l2b   = (const float*)d_in[20];
  const float* ln3w  = (const float*)d_in[21];
  const float* ln3b  = (const float*)d_in[22];
  const float* l3w   = (const float*)d_in[23];
  const float* l3b   = (const float*)d_in[24];
  const float* pjw   = (const float*)d_in[25];
  const float* pjb   = (const float*)d_in[26];
  const float* nrmw  = (const float*)d_in[27];
  float* out = (float*)d_out;

  const int SM_K2  = (11988 + 11664) * 4;        // 94608 B
  const int SM_K4  = (2*256*91 + 8280) * 4;      // 219488 B
  const int SM_TL  = 6*9216*2 + 2*13824*2;       // 165888 B
  const int SM_TH  = 92672;                      // stash dominates
  cudaFuncSetAttribute(k_conv3, cudaFuncAttributeMaxDynamicSharedMemorySize, SM_K2);
  cudaFuncSetAttribute(k_attn,  cudaFuncAttributeMaxDynamicSharedMemorySize, SM_K4);
  cudaFuncSetAttribute(t_lin,   cudaFuncAttributeMaxDynamicSharedMemorySize, SM_TL);
  cudaFuncSetAttribute(t_h3,    cudaFuncAttributeMaxDynamicSharedMemorySize, SM_TH);
  cudaFuncSetAttribute(t_proj,  cudaFuncAttributeMaxDynamicSharedMemorySize, SM_TL);

  // t_lin is launch #4 -> lands in the fixed ncu window
  k_pack180<<<(6*13824+255)/256,256>>>(lw, 0);
  k_pack180<<<(6*13824+255)/256,256>>>(pjw, 1);
  k_pack36<<<(2*10752+255)/256,256>>>(w3);
  t_lin<<<TOTPIX/128,256,SM_TL>>>(x, lb);
  k_pos<<<4,256>>>(ppw, ppb, ln1w, ln1b, l1w, l1b, ln2w, ln2b, l2w, l2b, ln3w, ln3b, l3w, l3b);
  k_rpb<<<384,256>>>();
  k_dfe1<<<TOTPIX/256,256>>>(x, w1, b1);
  k_conv3<<<dim3(16,16,4),256,SM_K2>>>(w2, b2);
  t_h3<<<TOTPIX/128,256,SM_TH>>>(b3);
  k_attn<<<NWIN,256,SM_K4>>>(sl_w, sl_b);
  t_proj<<<TOTPIX/128,256,SM_TL>>>(x, pjb, nrmw, out);
}

// round 7
// speedup vs baseline: 1.3006x; 1.1827x over previous
#include <cuda_runtime.h>
#include <cuda_bf16.h>
#include <math.h>
#include <stdint.h>

#define NBATCH 4
#define NCH    180
#define IMG    256
#define NPIX   (IMG*IMG)            // 65536
#define TOTPIX (NBATCH*NPIX)        // 262144
#define MIDC   36
#define NWIN   1024

// ---- scratch (device globals; no allocation allowed) ----
__device__ float g_h1[(size_t)TOTPIX*MIDC];
__device__ float g_h2[(size_t)TOTPIX*MIDC];
__device__ float g_qv[(size_t)TOTPIX*NCH];
__device__ float g_y [(size_t)TOTPIX*NCH];
__device__ float g_pos[961*6];
__device__ float g_rpb[6*256*64];
// packed bf16 weights, transposed [n][k] padded tiles
__device__ __align__(16) __nv_bfloat16 g_pk_lw[6*13824];  // [192][72] x (Bh0..2,Bl0..2)
__device__ __align__(16) __nv_bfloat16 g_pk_pj[6*13824];
__device__ __align__(16) __nv_bfloat16 g_pk_w3[2*10752];  // [192][56] x (hi,lo)

typedef unsigned long long u64;

__device__ __forceinline__ u64 pk2(float lo, float hi){
  u64 r; asm("mov.b64 %0,{%1,%2};" : "=l"(r) : "f"(lo), "f"(hi)); return r;
}
__device__ __forceinline__ u64 dup2(float v){ return pk2(v, v); }
__device__ __forceinline__ void up2(u64 v, float& lo, float& hi){
  asm("mov.b64 {%0,%1},%2;" : "=f"(lo), "=f"(hi) : "l"(v));
}
__device__ __forceinline__ u64 ffma2(u64 a, u64 b, u64 c){
  u64 d; asm("fma.rn.f32x2 %0,%1,%2,%3;" : "=l"(d) : "l"(a), "l"(b), "l"(c)); return d;
}
__device__ __forceinline__ u64 fmul2(u64 a, u64 b){
  u64 d; asm("mul.rn.f32x2 %0,%1,%2;" : "=l"(d) : "l"(a), "l"(b)); return d;
}
__device__ __forceinline__ float lrelu(float v){ return v >= 0.f ? v : 0.2f*v; }

__device__ __forceinline__ void cvhl(float v, __nv_bfloat16& h, __nv_bfloat16& l){
  h = __float2bfloat16(v);
  l = __float2bfloat16(v - __bfloat162float(h));
}

// ---- portable tensor-core primitives ----
#define MMA16816(c, a, b0, b1) \
  asm volatile("mma.sync.aligned.m16n8k16.row.col.f32.bf16.bf16.f32 " \
    "{%0,%1,%2,%3}, {%4,%5,%6,%7}, {%8,%9}, {%0,%1,%2,%3};" \
    : "+f"((c)[0]), "+f"((c)[1]), "+f"((c)[2]), "+f"((c)[3]) \
    : "r"((a)[0]), "r"((a)[1]), "r"((a)[2]), "r"((a)[3]), "r"(b0), "r"(b1))

__device__ __forceinline__ void ldsm_x4(uint32_t r[4], uint32_t saddr){
  asm volatile("ldmatrix.sync.aligned.m8n8.x4.shared.b16 {%0,%1,%2,%3}, [%4];"
    : "=r"(r[0]),"=r"(r[1]),"=r"(r[2]),"=r"(r[3]) : "r"(saddr));
}
__device__ __forceinline__ void cpa16(uint32_t d, const void* s){
  asm volatile("cp.async.cg.shared.global [%0], [%1], 16;" :: "r"(d), "l"(s));
}
#define CP_COMMIT() asm volatile("cp.async.commit_group;" ::: "memory")
#define CP_WAIT(n)  asm volatile("cp.async.wait_group %0;" :: "n"(n) : "memory")

// pipelined pass: A[64][K]@smem x B[192][K]^T@smem -> c (warp tile 32x48)
// wm in {0,1}, wn in {0..3}; strides in bf16 elems
template<int SA, int SB, int NKS>
__device__ __forceinline__ void mma_pass(uint32_t aBase, uint32_t bBase,
                                         float c[2][6][4], int lane, int wm, int wn){
  uint32_t aoff[2], boff[3];
  int ar = (lane&7) + ((lane&8)?8:0);
  int ak = (lane&16)?8:0;
#pragma unroll
  for (int mt=0;mt<2;mt++) aoff[mt] = aBase + (uint32_t)(((wm*32+mt*16+ar)*SA + ak)*2);
  int br = (lane&7) + ((lane&16)?8:0);
  int bk = (lane&8)?8:0;
#pragma unroll
  for (int p=0;p<3;p++) boff[p] = bBase + (uint32_t)(((wn*48+p*16+br)*SB + bk)*2);

  uint32_t a[2][2][4], b[2][3][4];
  ldsm_x4(a[0][0], aoff[0]);
  ldsm_x4(a[0][1], aoff[1]);
#pragma unroll
  for (int p=0;p<3;p++) ldsm_x4(b[0][p], boff[p]);
#pragma unroll
  for (int ks=0;ks<NKS;ks++){
    int cur = ks&1, nxt = cur^1;
    if (ks+1 < NKS){
      ldsm_x4(a[nxt][0], aoff[0] + (ks+1)*32);
      ldsm_x4(a[nxt][1], aoff[1] + (ks+1)*32);
#pragma unroll
      for (int p=0;p<3;p++) ldsm_x4(b[nxt][p], boff[p] + (ks+1)*32);
    }
#pragma unroll
    for (int p=0;p<3;p++){
      MMA16816(c[0][2*p],   a[cur][0], b[cur][p][0], b[cur][p][1]);
      MMA16816(c[1][2*p],   a[cur][1], b[cur][p][0], b[cur][p][1]);
      MMA16816(c[0][2*p+1], a[cur][0], b[cur][p][2], b[cur][p][3]);
      MMA16816(c[1][2*p+1], a[cur][1], b[cur][p][2], b[cur][p][3]);
    }
  }
}

// =============== pack kernels ===============
__global__ void k_pack180(const float* __restrict__ W, int which){
  __nv_bfloat16* dst = which ? g_pk_pj : g_pk_lw;
  int idx = blockIdx.x*256 + threadIdx.x;
  if (idx >= 6*13824) return;
  int cc = idx/13824, r = idx - cc*13824, n = r/72, k = r - n*72;
  int half = cc/3, kc = cc - half*3;
  int kk = kc*64 + k;
  float v = (n<180 && k<64 && kk<180) ? W[kk*180+n] : 0.f;
  __nv_bfloat16 h, l; cvhl(v, h, l);
  dst[idx] = half ? l : h;
}
__global__ void k_pack36(const float* __restrict__ W){
  int idx = blockIdx.x*256 + threadIdx.x;
  if (idx >= 2*10752) return;
  int cc = idx/10752, r = idx - cc*10752, n = r/56, k = r - n*56;
  float v = (n<180 && k<36) ? W[k*180+n] : 0.f;
  __nv_bfloat16 h, l; cvhl(v, h, l);
  g_pk_w3[idx] = cc ? l : h;
}

// =============== T1: t_lin: g_y = x @ lw + lb ===============
// 64 px/CTA; smem: A 6*9216B + B 2*27648B = 110592B -> 2 CTAs/SM
__global__ void __launch_bounds__(256,2) t_lin(const float* __restrict__ x,
                                               const float* __restrict__ lb){
  extern __shared__ __align__(16) char smc[];
  __nv_bfloat16* Ab = (__nv_bfloat16*)smc;                // 6*4608 bf16
  const uint32_t O_B0 = 6*4608*2, O_B1 = O_B0 + 13824*2;  // bytes
  uint32_t sbase = (uint32_t)__cvta_generic_to_shared(smc);
  int tid = threadIdx.x; int lane = tid&31, wid = tid>>5;
  int wm = wid&1, wn = wid>>1;
  int r0 = blockIdx.x*64; int bb = r0>>16; int p0 = r0&65535;

  for (int t=tid; t<1728; t+=256)
    cpa16(sbase + O_B0 + t*16, (const char*)(g_pk_lw) + t*16);
  CP_COMMIT();

  // A prologue: 192 ch x 64 px
  for (int idx=tid; idx<192*64; idx+=256){
    int c = idx>>6, px = idx&63;
    float v = (c<180) ? x[((size_t)(bb*180+c))*NPIX + p0+px] : 0.f;
    __nv_bfloat16 h,l; cvhl(v,h,l);
    int t = c>>6, k = c&63;
    Ab[t*4608 + px*72 + k]     = h;
    Ab[(t+3)*4608 + px*72 + k] = l;
  }
  float c[2][6][4];
#pragma unroll
  for (int mt=0;mt<2;mt++)
#pragma unroll
    for (int nt=0;nt<6;nt++)
#pragma unroll
      for (int e=0;e<4;e++) c[mt][nt][e]=0.f;

  for (int i=0;i<6;i++){
    uint32_t bo = (i&1) ? O_B1 : O_B0;
    if (i<5){
      uint32_t bn = ((i+1)&1) ? O_B1 : O_B0;
      for (int t=tid; t<1728; t+=256)
        cpa16(sbase + bn + t*16, (const char*)(g_pk_lw + (i+1)*13824) + t*16);
      CP_COMMIT();
      CP_WAIT(1);
    } else {
      CP_WAIT(0);
    }
    __syncthreads();
    if (i<3){
      mma_pass<72,72,4>(sbase + (uint32_t)(i*4608*2),     sbase + bo, c, lane, wm, wn);
      mma_pass<72,72,4>(sbase + (uint32_t)((3+i)*4608*2), sbase + bo, c, lane, wm, wn);
    } else {
      mma_pass<72,72,4>(sbase + (uint32_t)((i-3)*4608*2), sbase + bo, c, lane, wm, wn);
    }
    __syncthreads();
  }
  float* stash = (float*)smc;  // 64*181*4 = 46336 <= A region 55296
#pragma unroll
  for (int mt=0;mt<2;mt++){
    int r1 = wm*32 + mt*16 + (lane>>2);
#pragma unroll
    for (int nt=0;nt<6;nt++){
      int n0 = wn*48 + nt*8 + (lane&3)*2;
      if (n0 < 180){
        float bl0=__ldg(lb+n0), bl1=__ldg(lb+n0+1);
        stash[r1*181+n0]       = c[mt][nt][0]+bl0;
        stash[r1*181+n0+1]     = c[mt][nt][1]+bl1;
        stash[(r1+8)*181+n0]   = c[mt][nt][2]+bl0;
        stash[(r1+8)*181+n0+1] = c[mt][nt][3]+bl1;
      }
    }
  }
  __syncthreads();
  {
    int f = tid;
    int px = f/180, co = f - px*180;
    for (; f < 64*180; f += 256){
      g_y[(size_t)r0*180 + f] = stash[px*181+co];
      co += 256; if (co >= 180){ co -= 180; px++; if (co >= 180){ co -= 180; px++; } }
    }
  }
}

// =============== K0a: position-bias MLP ===============
__device__ __forceinline__ void ln_relu11(const float* in, const float* w, const float* b, float* out){
  float m = 0.f;
#pragma unroll
  for (int j=0;j<11;j++) m += in[j];
  m *= (1.f/11.f);
  float var = 0.f;
#pragma unroll
  for (int j=0;j<11;j++){ float d = in[j]-m; var += d*d; }
  var *= (1.f/11.f);
  float inv = rsqrtf(var + 1e-5f);
#pragma unroll
  for (int j=0;j<11;j++) out[j] = fmaxf((in[j]-m)*inv*w[j] + b[j], 0.f);
}

__global__ void k_pos(const float* __restrict__ pw, const float* __restrict__ pb,
                      const float* __restrict__ ln1w, const float* __restrict__ ln1b,
                      const float* __restrict__ w1,  const float* __restrict__ b1,
                      const float* __restrict__ ln2w, const float* __restrict__ ln2b,
                      const float* __restrict__ w2,  const float* __restrict__ b2,
                      const float* __restrict__ ln3w, const float* __restrict__ ln3b,
                      const float* __restrict__ w3,  const float* __restrict__ b3){
  int n = blockIdx.x*blockDim.x + threadIdx.x;
  if (n >= 961) return;
  float i0 = (float)(n/31) - 15.f;
  float i1 = (float)(n%31) - 15.f;
  float p[11], t[11];
#pragma unroll
  for (int j=0;j<11;j++) p[j] = i0*pw[j] + i1*pw[11+j] + pb[j];
  ln_relu11(p, ln1w, ln1b, t);
#pragma unroll
  for (int k=0;k<11;k++){ float s=b1[k];
#pragma unroll
    for (int j=0;j<11;j++) s += t[j]*w1[j*11+k]; p[k]=s; }
  ln_relu11(p, ln2w, ln2b, t);
#pragma unroll
  for (int k=0;k<11;k++){ float s=b2[k];
#pragma unroll
    for (int j=0;j<11;j++) s += t[j]*w2[j*11+k]; p[k]=s; }
  ln_relu11(p, ln3w, ln3b, t);
#pragma unroll
  for (int k=0;k<6;k++){ float s=b3[k];
#pragma unroll
    for (int j=0;j<11;j++) s += t[j]*w3[j*6+k];
    g_pos[n*6+k] = s; }
}

// =============== K0b: rpb ===============
__global__ void k_rpb(){
  int idx = blockIdx.x*blockDim.x + threadIdx.x;
  if (idx >= 6*256*64) return;
  int nh = idx/16384;
  int r  = idx - nh*16384;
  int l  = r>>6;
  int m  = r&63;
  int rl = l>>4, cl = l&15;
  int mh = m>>3, mw = m&7;
  float s = 0.f;
#pragma unroll
  for (int rh=0;rh<2;rh++)
#pragma unroll
    for (int rw=0;rw<2;rw++){
      int r2 = mh*2+rh, c2 = mw*2+rw;
      int k = (rl-r2+15)*31 + (cl-c2+15);
      s += g_pos[k*6+nh];
    }
  g_rpb[idx] = 0.25f*s;
}

// =============== K1: h1 = lrelu(x @ w1 + b1) ===============
__global__ void __launch_bounds__(256) k_dfe1(const float* __restrict__ x,
                                              const float* __restrict__ w1,
                                              const float* __restrict__ b1){
  __shared__ __align__(16) float ws[180*36];
  int tid = threadIdx.x;
  for (int t=tid;t<180*36;t+=256) ws[t]=w1[t];
  __syncthreads();
  int r = blockIdx.x*256 + tid;
  int b = r>>16; int p = r&65535;
  const float* xp = x + (size_t)b*NCH*NPIX + p;
  u64 acc2[18];
#pragma unroll
  for (int q=0;q<18;q++) acc2[q] = pk2(b1[2*q], b1[2*q+1]);
  for (int ci=0;ci<180;ci++){
    u64 v2 = dup2(xp[(size_t)ci*NPIX]);
    const ulonglong2* wr = (const ulonglong2*)(ws + ci*36);
#pragma unroll
    for (int q=0;q<9;q++){
      ulonglong2 w = wr[q];
      acc2[2*q]   = ffma2(v2, w.x, acc2[2*q]);
      acc2[2*q+1] = ffma2(v2, w.y, acc2[2*q+1]);
    }
  }
  float2* dst = (float2*)(g_h1 + (size_t)r*36);
#pragma unroll
  for (int q=0;q<18;q++){
    float lo,hi; up2(acc2[q], lo, hi);
    dst[q] = make_float2(lrelu(lo), lrelu(hi));
  }
}

// =============== K2: h2 = lrelu(conv3x3(h1)) ===============
__global__ void __launch_bounds__(256) k_conv3(const float* __restrict__ w2,
                                               const float* __restrict__ b2){
  extern __shared__ float sm2[];
  float* ins = sm2;             // 18*18*37
  float* wsh = sm2 + 11988;     // 9*36*36
  int tid = threadIdx.x;
  int b = blockIdx.z; int hy0 = blockIdx.y*16, wx0 = blockIdx.x*16;
  for (int t=tid;t<18*18*36;t+=256){
    int ci = t%36; int rc = t/36; int col = rc%18; int row = rc/18;
    int gh = hy0+row-1, gw = wx0+col-1;
    float v = 0.f;
    if (gh>=0 && gh<IMG && gw>=0 && gw<IMG)
      v = g_h1[((size_t)(b*IMG+gh)*IMG+gw)*36 + ci];
    ins[(row*18+col)*37+ci] = v;
  }
  for (int t=tid;t<9*36*36;t+=256) wsh[t] = w2[t];
  __syncthreads();
  int tx = tid&15, ty = tid>>4;
  float acc[36];
#pragma unroll
  for (int co=0;co<36;co++) acc[co] = b2[co];
  for (int dy=0;dy<3;dy++)
    for (int dx=0;dx<3;dx++){
      const float* wp = wsh + (dy*3+dx)*36*36;
      const float* ip = ins + ((ty+dy)*18 + tx+dx)*37;
      for (int ci=0;ci<36;ci++){
        float v = ip[ci];
        const float* wr = wp + ci*36;
#pragma unroll
        for (int co=0;co<36;co++) acc[co] += v*wr[co];
      }
    }
  size_t o = ((size_t)(b*IMG+hy0+ty)*IMG + wx0+tx)*36;
  float4* dst = (float4*)(g_h2 + o);
#pragma unroll
  for (int q=0;q<9;q++){
    float4 r; r.x=lrelu(acc[q*4]); r.y=lrelu(acc[q*4+1]); r.z=lrelu(acc[q*4+2]); r.w=lrelu(acc[q*4+3]);
    dst[q]=r;
  }
}

// =============== T2: t_h3: g_qv = (h2 @ w3 + b3) * g_y ===============
// 64 px/CTA; smem: A 14336B + B 43008B = 57344B
__global__ void __launch_bounds__(256,2) t_h3(const float* __restrict__ b3){
  extern __shared__ __align__(16) char smc[];
  __nv_bfloat16* Ab = (__nv_bfloat16*)smc;    // hi @0, lo @3584 elems
  const uint32_t O_B = 7168*2;                // B hi @0, lo @10752 elems after
  uint32_t sbase = (uint32_t)__cvta_generic_to_shared(smc);
  int tid = threadIdx.x; int lane = tid&31, wid = tid>>5;
  int wm = wid&1, wn = wid>>1;
  int r0 = blockIdx.x*64;

  for (int t=tid; t<2688; t+=256)
    cpa16(sbase + O_B + t*16, (const char*)(g_pk_w3) + t*16);
  CP_COMMIT();

  for (int idx=tid; idx<64*48; idx+=256){
    int px = idx/48, cc = idx - px*48;
    float v = (cc<36) ? g_h2[(size_t)(r0+px)*36 + cc] : 0.f;
    __nv_bfloat16 h,l; cvhl(v,h,l);
    Ab[px*56 + cc]        = h;
    Ab[3584 + px*56 + cc] = l;
  }
  CP_WAIT(0);
  __syncthreads();
  float c[2][6][4];
#pragma unroll
  for (int mt=0;mt<2;mt++)
#pragma unroll
    for (int nt=0;nt<6;nt++)
#pragma unroll
      for (int e=0;e<4;e++) c[mt][nt][e]=0.f;

  mma_pass<56,56,3>(sbase,           sbase + O_B,           c, lane, wm, wn); // Ah,Bh
  mma_pass<56,56,3>(sbase + 3584*2,  sbase + O_B,           c, lane, wm, wn); // Al,Bh
  mma_pass<56,56,3>(sbase,           sbase + O_B + 10752*2, c, lane, wm, wn); // Ah,Bl
  __syncthreads();
  float* stash = (float*)smc;    // 46336 <= 57344
#pragma unroll
  for (int mt=0;mt<2;mt++){
    int r1 = wm*32 + mt*16 + (lane>>2);
#pragma unroll
    for (int nt=0;nt<6;nt++){
      int n0 = wn*48 + nt*8 + (lane&3)*2;
      if (n0 < 180){
        float b30=__ldg(b3+n0), b31=__ldg(b3+n0+1);
        stash[r1*181+n0]       = c[mt][nt][0]+b30;
        stash[r1*181+n0+1]     = c[mt][nt][1]+b31;
        stash[(r1+8)*181+n0]   = c[mt][nt][2]+b30;
        stash[(r1+8)*181+n0+1] = c[mt][nt][3]+b31;
      }
    }
  }
  __syncthreads();
  {
    int f = tid;
    int px = f/180, co = f - px*180;
    for (; f < 64*180; f += 256){
      g_qv[(size_t)r0*180 + f] = stash[px*181+co] * g_y[(size_t)r0*180 + f];
      co += 256; if (co >= 180){ co -= 180; px++; if (co >= 180){ co -= 180; px++; } }
    }
  }
}

// =============== K4: per-window attention ===============
__global__ void __launch_bounds__(256) k_attn(const float* __restrict__ sl_w,
                                              const float* __restrict__ sl_b){
  extern __shared__ float sm4[];
  float* QS = sm4;
  float* VS = sm4 + 256*91;
  float* SC = sm4 + 2*256*91;
  int tid = threadIdx.x;
  int bw = blockIdx.x;
  int b = bw>>8, wy = (bw>>4)&15, wx = bw&15;
  int l = tid;
  int gh = wy*16 + (l>>4), gw = wx*16 + (l&15);
  size_t pix = ((size_t)(b*IMG+gh))*IMG + gw;
  {
    const float4* src = (const float4*)(g_qv + pix*180);
#pragma unroll
    for (int k=0;k<45;k++){
      float4 v4 = src[k];
      int c0 = k*4;
      float vals[4] = {v4.x,v4.y,v4.z,v4.w};
#pragma unroll
      for (int e=0;e<4;e++){
        int c = c0+e;
        if (c < 90) QS[l*91+c] = vals[e];
        else        VS[l*91+(c-90)] = vals[e];
      }
    }
  }
  __syncthreads();
  float slw0=sl_w[0], slw1=sl_w[1], slw2=sl_w[2], slw3=sl_w[3], slb=sl_b[0];
  for (int idx=tid; idx<6144; idx+=256){
    int nh = idx>>10; int r = idx & 1023; int m = r>>4; int hd = r&15;
    float val = 0.f;
    if (hd < 15){
      int mh = m>>3, mw = m&7; int ch = nh*15+hd;
      int l00 = (mh*2)*16 + mw*2;
      val = slb + slw0*VS[l00*91+ch]      + slw1*VS[(l00+1)*91+ch]
                + slw2*VS[(l00+16)*91+ch] + slw3*VS[(l00+17)*91+ch];
    }
    SC[idx] = val;
  }
  __syncthreads();
  {
    float* ydst = g_y + pix*180;
    for (int nh=0; nh<6; nh++){
      float qs[15];
#pragma unroll
      for (int hd=0;hd<15;hd++) qs[hd] = QS[l*91 + nh*15 + hd];
      u64 q2[8];
#pragma unroll
      for (int p=0;p<7;p++) q2[p] = pk2(qs[2*p], qs[2*p+1]);
      q2[7] = pk2(qs[14], 0.f);
      const float* vp = SC + (nh<<10);
      const float* rpbrow = g_rpb + ((size_t)((nh<<8) + l))*64;
      u64 xs2[8];
#pragma unroll
      for (int p=0;p<8;p++) xs2[p]=0ull;
      for (int m0=0;m0<64;m0+=4){
        float4 rb = *(const float4*)(rpbrow + m0);
        float rbv[4] = {rb.x, rb.y, rb.z, rb.w};
#pragma unroll
        for (int t=0;t<4;t++){
          const ulonglong2* vpp = (const ulonglong2*)(vp + ((m0+t)<<4));
          ulonglong2 wA = vpp[0], wB = vpp[1], wC = vpp[2], wD = vpp[3];
          u64 d2 = fmul2(q2[0], wA.x);
          d2 = ffma2(q2[1], wA.y, d2);
          d2 = ffma2(q2[2], wB.x, d2);
          d2 = ffma2(q2[3], wB.y, d2);
          d2 = ffma2(q2[4], wC.x, d2);
          d2 = ffma2(q2[5], wC.y, d2);
          d2 = ffma2(q2[6], wD.x, d2);
          d2 = ffma2(q2[7], wD.y, d2);
          float lo,hi; up2(d2, lo, hi);
          u64 s2 = dup2((lo+hi)*(1.f/15.f) + rbv[t]);
          xs2[0] = ffma2(s2, wA.x, xs2[0]);
          xs2[1] = ffma2(s2, wA.y, xs2[1]);
          xs2[2] = ffma2(s2, wB.x, xs2[2]);
          xs2[3] = ffma2(s2, wB.y, xs2[3]);
          xs2[4] = ffma2(s2, wC.x, xs2[4]);
          xs2[5] = ffma2(s2, wC.y, xs2[5]);
          xs2[6] = ffma2(s2, wD.x, xs2[6]);
          xs2[7] = ffma2(s2, wD.y, xs2[7]);
        }
      }
#pragma unroll
      for (int p=0;p<7;p++){
        float lo,hi; up2(xs2[p], lo, hi);
        ydst[nh*15+2*p] = lo; ydst[nh*15+2*p+1] = hi;
      }
      { float lo,hi; up2(xs2[7], lo, hi); ydst[nh*15+14] = lo; }
    }
  }
  u64 cm2[6][3];
  int cb=0, db=0;
  bool act = (tid < 225);
  if (act){
    cb = (tid/15)*6; db = (tid%15)*6;
#pragma unroll
    for (int i=0;i<6;i++)
#pragma unroll
      for (int t=0;t<3;t++) cm2[i][t]=0ull;
    for (int ll=0; ll<256; ll++){
      u64 qr[6];
#pragma unroll
      for (int i=0;i<6;i++) qr[i] = dup2(QS[ll*91+cb+i]);
      u64 vr[3];
#pragma unroll
      for (int t=0;t<3;t++) vr[t] = pk2(VS[ll*91+db+2*t], VS[ll*91+db+2*t+1]);
#pragma unroll
      for (int i=0;i<6;i++)
#pragma unroll
        for (int t=0;t<3;t++) cm2[i][t] = ffma2(qr[i], vr[t], cm2[i][t]);
    }
  }
  __syncthreads();
  if (act){
#pragma unroll
    for (int i=0;i<6;i++)
#pragma unroll
      for (int t=0;t<3;t++){
        float lo,hi; up2(cm2[i][t], lo, hi);
        SC[(db+2*t  )*92 + cb+i] = lo*(1.f/256.f);
        SC[(db+2*t+1)*92 + cb+i] = hi*(1.f/256.f);
      }
  }
  __syncthreads();
  {
    float* ydst = g_y + pix*180 + 90;
    for (int c0=0;c0<90;c0+=18){
      u64 s2[9];
#pragma unroll
      for (int t=0;t<9;t++) s2[t]=0ull;
      for (int d=0; d<90; d++){
        u64 v2 = dup2(VS[l*91+d]);
        const u64* cp = (const u64*)(SC + d*92 + c0);
#pragma unroll
        for (int t=0;t<9;t++) s2[t] = ffma2(v2, cp[t], s2[t]);
      }
#pragma unroll
      for (int t=0;t<9;t++){
        float lo,hi; up2(s2[t], lo, hi);
        ydst[c0+2*t] = lo; ydst[c0+2*t+1] = hi;
      }
    }
  }
}

// =============== T3: t_proj: out = x + RMSNorm(g_y@pjw + pb)*nw ===============
__global__ void __launch_bounds__(256,2) t_proj(const float* __restrict__ x,
                                                const float* __restrict__ pb,
                                                const float* __restrict__ nw,
                                                float* __restrict__ out){
  extern __shared__ __align__(16) char smc[];
  __shared__ float scl[64];
  __nv_bfloat16* Ab = (__nv_bfloat16*)smc;
  const uint32_t O_B0 = 6*4608*2, O_B1 = O_B0 + 13824*2;
  uint32_t sbase = (uint32_t)__cvta_generic_to_shared(smc);
  int tid = threadIdx.x; int lane = tid&31, wid = tid>>5;
  int wm = wid&1, wn = wid>>1;
  int r0 = blockIdx.x*64; int bb = r0>>16; int p0 = r0&65535;

  for (int t=tid; t<1728; t+=256)
    cpa16(sbase + O_B0 + t*16, (const char*)(g_pk_pj) + t*16);
  CP_COMMIT();

  for (int idx=tid; idx<64*192; idx+=256){
    int px = idx/192, cc = idx - px*192;
    float v = (cc<180) ? g_y[(size_t)(r0+px)*180 + cc] : 0.f;
    __nv_bfloat16 h,l; cvhl(v,h,l);
    int t = cc>>6, k = cc&63;
    Ab[t*4608 + px*72 + k]     = h;
    Ab[(t+3)*4608 + px*72 + k] = l;
  }
  float c[2][6][4];
#pragma unroll
  for (int mt=0;mt<2;mt++)
#pragma unroll
    for (int nt=0;nt<6;nt++)
#pragma unroll
      for (int e=0;e<4;e++) c[mt][nt][e]=0.f;

  for (int i=0;i<6;i++){
    uint32_t bo = (i&1) ? O_B1 : O_B0;
    if (i<5){
      uint32_t bn = ((i+1)&1) ? O_B1 : O_B0;
      for (int t=tid; t<1728; t+=256)
        cpa16(sbase + bn + t*16, (const char*)(g_pk_pj + (i+1)*13824) + t*16);
      CP_COMMIT();
      CP_WAIT(1);
    } else {
      CP_WAIT(0);
    }
    __syncthreads();
    if (i<3){
      mma_pass<72,72,4>(sbase + (uint32_t)(i*4608*2),     sbase + bo, c, lane, wm, wn);
      mma_pass<72,72,4>(sbase + (uint32_t)((3+i)*4608*2), sbase + bo, c, lane, wm, wn);
    } else {
      mma_pass<72,72,4>(sbase + (uint32_t)((i-3)*4608*2), sbase + bo, c, lane, wm, wn);
    }
    __syncthreads();
  }
  float* stash = (float*)smc;
#pragma unroll
  for (int mt=0;mt<2;mt++){
    int r1 = wm*32 + mt*16 + (lane>>2);
#pragma unroll
    for (int nt=0;nt<6;nt++){
      int n0 = wn*48 + nt*8 + (lane&3)*2;
      if (n0 < 180){
        float b0=__ldg(pb+n0), b1=__ldg(pb+n0+1);
        stash[r1*181+n0]       = c[mt][nt][0]+b0;
        stash[r1*181+n0+1]     = c[mt][nt][1]+b1;
        stash[(r1+8)*181+n0]   = c[mt][nt][2]+b0;
        stash[(r1+8)*181+n0+1] = c[mt][nt][3]+b1;
      }
    }
  }
  __syncthreads();
  if (tid < 64){
    const float* row = stash + tid*181;
    float s = 0.f;
    for (int cc=0; cc<180; cc++){ float v = row[cc]; s += v*v; }
    scl[tid] = rsqrtf(s*(1.f/180.f) + 1.1920929e-07f);
  }
  __syncthreads();
  {
    int px = tid&63;
    int q = tid>>6;   // 0..3
    float sc = scl[px];
    for (int ci=q; ci<180; ci+=4){
      size_t a = ((size_t)(bb*180+ci))*NPIX + p0 + px;
      out[a] = x[a] + stash[px*181+ci]*sc*__ldg(nw+ci);
    }
  }
}

// =============== launch ===============
extern "C" void kernel_launch(void* const* d_in, const int* in_sizes, int n_in,
                              void* d_out, int out_size){
  const float* x     = (const float*)d_in[0];
  const float* w1    = (const float*)d_in[1];
  const float* b1    = (const float*)d_in[2];
  const float* w2    = (const float*)d_in[3];
  const float* b2    = (const float*)d_in[4];
  const float* w3    = (const float*)d_in[5];
  const float* b3    = (const float*)d_in[6];
  const float* lw    = (const float*)d_in[7];
  const float* lb    = (const float*)d_in[8];
  const float* sl_w  = (const float*)d_in[9];
  const float* sl_b  = (const float*)d_in[10];
  const float* ppw   = (const float*)d_in[11];
  const float* ppb   = (const float*)d_in[12];
  const float* ln1w  = (const float*)d_in[13];
  const float* ln1b  = (const float*)d_in[14];
  const float* l1w   = (const float*)d_in[15];
  const float* l1b   = (const float*)d_in[16];
  const float* ln2w  = (const float*)d_in[17];
  const float* ln2b  = (const float*)d_in[18];
  const float* l2w   = (const float*)d_in[19];
  const float* l2b   = (const float*)d_in[20];
  const float* ln3w  = (const float*)d_in[21];
  const float* ln3b  = (const float*)d_in[22];
  const float* l3w   = (const float*)d_in[23];
  const float* l3b   = (const float*)d_in[24];
  const float* pjw   = (const float*)d_in[25];
  const float* pjb   = (const float*)d_in[26];
  const float* nrmw  = (const float*)d_in[27];
  float* out = (float*)d_out;

  const int SM_K2  = (11988 + 11664) * 4;        // 94608 B
  const int SM_K4  = (2*256*91 + 8280) * 4;      // 219488 B
  const int SM_TL  = 6*4608*2 + 2*13824*2;       // 110592 B
  const int SM_TH  = 7168*2*2 + 2*10752*2;       // 71680 B  (A 28672 + B 43008)
  cudaFuncSetAttribute(k_conv3, cudaFuncAttributeMaxDynamicSharedMemorySize, SM_K2);
  cudaFuncSetAttribute(k_attn,  cudaFuncAttributeMaxDynamicSharedMemorySize, SM_K4);
  cudaFuncSetAttribute(t_lin,   cudaFuncAttributeMaxDynamicSharedMemorySize, SM_TL);
  cudaFuncSetAttribute(t_h3,    cudaFuncAttributeMaxDynamicSharedMemorySize, SM_TH);
  cudaFuncSetAttribute(t_proj,  cudaFuncAttributeMaxDynamicSharedMemorySize, SM_TL);

  // t_lin stays launch #4 -> lands in the fixed ncu window
  k_pack180<<<(6*13824+255)/256,256>>>(lw, 0);
  k_pack180<<<(6*13824+255)/256,256>>>(pjw, 1);
  k_pack36<<<(2*10752+255)/256,256>>>(w3);
  t_lin<<<TOTPIX/64,256,SM_TL>>>(x, lb);
  k_pos<<<4,256>>>(ppw, ppb, ln1w, ln1b, l1w, l1b, ln2w, ln2b, l2w, l2b, ln3w, ln3b, l3w, l3b);
  k_rpb<<<384,256>>>();
  k_dfe1<<<TOTPIX/256,256>>>(x, w1, b1);
  k_conv3<<<dim3(16,16,4),256,SM_K2>>>(w2, b2);
  t_h3<<<TOTPIX/64,256,SM_TH>>>(b3);
  k_attn<<<NWIN,256,SM_K4>>>(sl_w, sl_b);
  t_proj<<<TOTPIX/64,256,SM_TL>>>(x, pjb, nrmw, out);
}

// round 8
// speedup vs baseline: 1.3413x; 1.0313x over previous
#include <cuda_runtime.h>
#include <cuda_bf16.h>
#include <math.h>
#include <stdint.h>

#define NBATCH 4
#define NCH    180
#define IMG    256
#define NPIX   (IMG*IMG)            // 65536
#define TOTPIX (NBATCH*NPIX)        // 262144
#define MIDC   36
#define NWIN   1024

// ---- scratch (device globals; no allocation allowed) ----
__device__ float g_h1[(size_t)TOTPIX*MIDC];
__device__ float g_h2[(size_t)TOTPIX*MIDC];
__device__ float g_qv[(size_t)TOTPIX*NCH];
__device__ float g_y [(size_t)TOTPIX*NCH];
__device__ float g_pos[961*6];
__device__ float g_rpb[6*256*64];
// packed bf16 weights, transposed [n][k] padded tiles
__device__ __align__(16) __nv_bfloat16 g_pk_lw[6*13824];  // [192][72] x (Bh0..2,Bl0..2)
__device__ __align__(16) __nv_bfloat16 g_pk_pj[6*13824];
__device__ __align__(16) __nv_bfloat16 g_pk_w3[2*10752];  // [192][56] x (hi,lo)

typedef unsigned long long u64;

__device__ __forceinline__ u64 pk2(float lo, float hi){
  u64 r; asm("mov.b64 %0,{%1,%2};" : "=l"(r) : "f"(lo), "f"(hi)); return r;
}
__device__ __forceinline__ u64 dup2(float v){ return pk2(v, v); }
__device__ __forceinline__ void up2(u64 v, float& lo, float& hi){
  asm("mov.b64 {%0,%1},%2;" : "=f"(lo), "=f"(hi) : "l"(v));
}
__device__ __forceinline__ u64 ffma2(u64 a, u64 b, u64 c){
  u64 d; asm("fma.rn.f32x2 %0,%1,%2,%3;" : "=l"(d) : "l"(a), "l"(b), "l"(c)); return d;
}
__device__ __forceinline__ u64 fmul2(u64 a, u64 b){
  u64 d; asm("mul.rn.f32x2 %0,%1,%2;" : "=l"(d) : "l"(a), "l"(b)); return d;
}
__device__ __forceinline__ float lrelu(float v){ return v >= 0.f ? v : 0.2f*v; }

__device__ __forceinline__ void cvhl(float v, __nv_bfloat16& h, __nv_bfloat16& l){
  h = __float2bfloat16(v);
  l = __float2bfloat16(v - __bfloat162float(h));
}

// ---- portable tensor-core primitives ----
#define MMA16816(c, a, b0, b1) \
  asm volatile("mma.sync.aligned.m16n8k16.row.col.f32.bf16.bf16.f32 " \
    "{%0,%1,%2,%3}, {%4,%5,%6,%7}, {%8,%9}, {%0,%1,%2,%3};" \
    : "+f"((c)[0]), "+f"((c)[1]), "+f"((c)[2]), "+f"((c)[3]) \
    : "r"((a)[0]), "r"((a)[1]), "r"((a)[2]), "r"((a)[3]), "r"(b0), "r"(b1))

__device__ __forceinline__ void ldsm_x4(uint32_t r[4], uint32_t saddr){
  asm volatile("ldmatrix.sync.aligned.m8n8.x4.shared.b16 {%0,%1,%2,%3}, [%4];"
    : "=r"(r[0]),"=r"(r[1]),"=r"(r[2]),"=r"(r[3]) : "r"(saddr));
}
__device__ __forceinline__ void cpa16(uint32_t d, const void* s){
  asm volatile("cp.async.cg.shared.global [%0], [%1], 16;" :: "r"(d), "l"(s));
}
#define CP_COMMIT() asm volatile("cp.async.commit_group;" ::: "memory")
#define CP_WAIT(n)  asm volatile("cp.async.wait_group %0;" :: "n"(n) : "memory")

// pipelined pass: A[64][K]@smem x B[192][K]^T@smem -> c (warp tile 32x48)
template<int SA, int SB, int NKS>
__device__ __forceinline__ void mma_pass(uint32_t aBase, uint32_t bBase,
                                         float c[2][6][4], int lane, int wm, int wn){
  uint32_t aoff[2], boff[3];
  int ar = (lane&7) + ((lane&8)?8:0);
  int ak = (lane&16)?8:0;
#pragma unroll
  for (int mt=0;mt<2;mt++) aoff[mt] = aBase + (uint32_t)(((wm*32+mt*16+ar)*SA + ak)*2);
  int br = (lane&7) + ((lane&16)?8:0);
  int bk = (lane&8)?8:0;
#pragma unroll
  for (int p=0;p<3;p++) boff[p] = bBase + (uint32_t)(((wn*48+p*16+br)*SB + bk)*2);

  uint32_t a[2][2][4], b[2][3][4];
  ldsm_x4(a[0][0], aoff[0]);
  ldsm_x4(a[0][1], aoff[1]);
#pragma unroll
  for (int p=0;p<3;p++) ldsm_x4(b[0][p], boff[p]);
#pragma unroll
  for (int ks=0;ks<NKS;ks++){
    int cur = ks&1, nxt = cur^1;
    if (ks+1 < NKS){
      ldsm_x4(a[nxt][0], aoff[0] + (ks+1)*32);
      ldsm_x4(a[nxt][1], aoff[1] + (ks+1)*32);
#pragma unroll
      for (int p=0;p<3;p++) ldsm_x4(b[nxt][p], boff[p] + (ks+1)*32);
    }
#pragma unroll
    for (int p=0;p<3;p++){
      MMA16816(c[0][2*p],   a[cur][0], b[cur][p][0], b[cur][p][1]);
      MMA16816(c[1][2*p],   a[cur][1], b[cur][p][0], b[cur][p][1]);
      MMA16816(c[0][2*p+1], a[cur][0], b[cur][p][2], b[cur][p][3]);
      MMA16816(c[1][2*p+1], a[cur][1], b[cur][p][2], b[cur][p][3]);
    }
  }
}

// =============== pack kernels ===============
__global__ void k_pack180(const float* __restrict__ W, int which){
  __nv_bfloat16* dst = which ? g_pk_pj : g_pk_lw;
  int idx = blockIdx.x*256 + threadIdx.x;
  if (idx >= 6*13824) return;
  int cc = idx/13824, r = idx - cc*13824, n = r/72, k = r - n*72;
  int half = cc/3, kc = cc - half*3;
  int kk = kc*64 + k;
  float v = (n<180 && k<64 && kk<180) ? W[kk*180+n] : 0.f;
  __nv_bfloat16 h, l; cvhl(v, h, l);
  dst[idx] = half ? l : h;
}
__global__ void k_pack36(const float* __restrict__ W){
  int idx = blockIdx.x*256 + threadIdx.x;
  if (idx >= 2*10752) return;
  int cc = idx/10752, r = idx - cc*10752, n = r/56, k = r - n*56;
  float v = (n<180 && k<36) ? W[k*180+n] : 0.f;
  __nv_bfloat16 h, l; cvhl(v, h, l);
  g_pk_w3[idx] = cc ? l : h;
}

// =============== K1: h1 = lrelu(x @ w1 + b1) ===============
__global__ void __launch_bounds__(256) k_dfe1(const float* __restrict__ x,
                                              const float* __restrict__ w1,
                                              const float* __restrict__ b1){
  __shared__ __align__(16) float ws[180*36];
  int tid = threadIdx.x;
  for (int t=tid;t<180*36;t+=256) ws[t]=w1[t];
  __syncthreads();
  int r = blockIdx.x*256 + tid;
  int b = r>>16; int p = r&65535;
  const float* xp = x + (size_t)b*NCH*NPIX + p;
  u64 acc2[18];
#pragma unroll
  for (int q=0;q<18;q++) acc2[q] = pk2(b1[2*q], b1[2*q+1]);
  for (int ci=0;ci<180;ci++){
    u64 v2 = dup2(xp[(size_t)ci*NPIX]);
    const ulonglong2* wr = (const ulonglong2*)(ws + ci*36);
#pragma unroll
    for (int q=0;q<9;q++){
      ulonglong2 w = wr[q];
      acc2[2*q]   = ffma2(v2, w.x, acc2[2*q]);
      acc2[2*q+1] = ffma2(v2, w.y, acc2[2*q+1]);
    }
  }
  float2* dst = (float2*)(g_h1 + (size_t)r*36);
#pragma unroll
  for (int q=0;q<18;q++){
    float lo,hi; up2(acc2[q], lo, hi);
    dst[q] = make_float2(lrelu(lo), lrelu(hi));
  }
}

// =============== T1: t_lin: g_y = x @ lw + lb ===============
__global__ void __launch_bounds__(256,2) t_lin(const float* __restrict__ x,
                                               const float* __restrict__ lb){
  extern __shared__ __align__(16) char smc[];
  __nv_bfloat16* Ab = (__nv_bfloat16*)smc;                // 6*4608 bf16
  const uint32_t O_B0 = 6*4608*2, O_B1 = O_B0 + 13824*2;  // bytes
  uint32_t sbase = (uint32_t)__cvta_generic_to_shared(smc);
  int tid = threadIdx.x; int lane = tid&31, wid = tid>>5;
  int wm = wid&1, wn = wid>>1;
  int r0 = blockIdx.x*64; int bb = r0>>16; int p0 = r0&65535;

  for (int t=tid; t<1728; t+=256)
    cpa16(sbase + O_B0 + t*16, (const char*)(g_pk_lw) + t*16);
  CP_COMMIT();

  for (int idx=tid; idx<192*64; idx+=256){
    int c = idx>>6, px = idx&63;
    float v = (c<180) ? x[((size_t)(bb*180+c))*NPIX + p0+px] : 0.f;
    __nv_bfloat16 h,l; cvhl(v,h,l);
    int t = c>>6, k = c&63;
    Ab[t*4608 + px*72 + k]     = h;
    Ab[(t+3)*4608 + px*72 + k] = l;
  }
  float c[2][6][4];
#pragma unroll
  for (int mt=0;mt<2;mt++)
#pragma unroll
    for (int nt=0;nt<6;nt++)
#pragma unroll
      for (int e=0;e<4;e++) c[mt][nt][e]=0.f;

  for (int i=0;i<6;i++){
    uint32_t bo = (i&1) ? O_B1 : O_B0;
    if (i<5){
      uint32_t bn = ((i+1)&1) ? O_B1 : O_B0;
      for (int t=tid; t<1728; t+=256)
        cpa16(sbase + bn + t*16, (const char*)(g_pk_lw + (i+1)*13824) + t*16);
      CP_COMMIT();
      CP_WAIT(1);
    } else {
      CP_WAIT(0);
    }
    __syncthreads();
    if (i<3){
      mma_pass<72,72,4>(sbase + (uint32_t)(i*4608*2),     sbase + bo, c, lane, wm, wn);
      mma_pass<72,72,4>(sbase + (uint32_t)((3+i)*4608*2), sbase + bo, c, lane, wm, wn);
    } else {
      mma_pass<72,72,4>(sbase + (uint32_t)((i-3)*4608*2), sbase + bo, c, lane, wm, wn);
    }
    __syncthreads();
  }
  float* stash = (float*)smc;
#pragma unroll
  for (int mt=0;mt<2;mt++){
    int r1 = wm*32 + mt*16 + (lane>>2);
#pragma unroll
    for (int nt=0;nt<6;nt++){
      int n0 = wn*48 + nt*8 + (lane&3)*2;
      if (n0 < 180){
        float bl0=__ldg(lb+n0), bl1=__ldg(lb+n0+1);
        stash[r1*181+n0]       = c[mt][nt][0]+bl0;
        stash[r1*181+n0+1]     = c[mt][nt][1]+bl1;
        stash[(r1+8)*181+n0]   = c[mt][nt][2]+bl0;
        stash[(r1+8)*181+n0+1] = c[mt][nt][3]+bl1;
      }
    }
  }
  __syncthreads();
  {
    int f = tid;
    int px = f/180, co = f - px*180;
    for (; f < 64*180; f += 256){
      g_y[(size_t)r0*180 + f] = stash[px*181+co];
      co += 256; if (co >= 180){ co -= 180; px++; if (co >= 180){ co -= 180; px++; } }
    }
  }
}

// =============== K0a: position-bias MLP ===============
__device__ __forceinline__ void ln_relu11(const float* in, const float* w, const float* b, float* out){
  float m = 0.f;
#pragma unroll
  for (int j=0;j<11;j++) m += in[j];
  m *= (1.f/11.f);
  float var = 0.f;
#pragma unroll
  for (int j=0;j<11;j++){ float d = in[j]-m; var += d*d; }
  var *= (1.f/11.f);
  float inv = rsqrtf(var + 1e-5f);
#pragma unroll
  for (int j=0;j<11;j++) out[j] = fmaxf((in[j]-m)*inv*w[j] + b[j], 0.f);
}

__global__ void k_pos(const float* __restrict__ pw, const float* __restrict__ pb,
                      const float* __restrict__ ln1w, const float* __restrict__ ln1b,
                      const float* __restrict__ w1,  const float* __restrict__ b1,
                      const float* __restrict__ ln2w, const float* __restrict__ ln2b,
                      const float* __restrict__ w2,  const float* __restrict__ b2,
                      const float* __restrict__ ln3w, const float* __restrict__ ln3b,
                      const float* __restrict__ w3,  const float* __restrict__ b3){
  int n = blockIdx.x*blockDim.x + threadIdx.x;
  if (n >= 961) return;
  float i0 = (float)(n/31) - 15.f;
  float i1 = (float)(n%31) - 15.f;
  float p[11], t[11];
#pragma unroll
  for (int j=0;j<11;j++) p[j] = i0*pw[j] + i1*pw[11+j] + pb[j];
  ln_relu11(p, ln1w, ln1b, t);
#pragma unroll
  for (int k=0;k<11;k++){ float s=b1[k];
#pragma unroll
    for (int j=0;j<11;j++) s += t[j]*w1[j*11+k]; p[k]=s; }
  ln_relu11(p, ln2w, ln2b, t);
#pragma unroll
  for (int k=0;k<11;k++){ float s=b2[k];
#pragma unroll
    for (int j=0;j<11;j++) s += t[j]*w2[j*11+k]; p[k]=s; }
  ln_relu11(p, ln3w, ln3b, t);
#pragma unroll
  for (int k=0;k<6;k++){ float s=b3[k];
#pragma unroll
    for (int j=0;j<11;j++) s += t[j]*w3[j*6+k];
    g_pos[n*6+k] = s; }
}

// =============== K0b: rpb ===============
__global__ void k_rpb(){
  int idx = blockIdx.x*blockDim.x + threadIdx.x;
  if (idx >= 6*256*64) return;
  int nh = idx/16384;
  int r  = idx - nh*16384;
  int l  = r>>6;
  int m  = r&63;
  int rl = l>>4, cl = l&15;
  int mh = m>>3, mw = m&7;
  float s = 0.f;
#pragma unroll
  for (int rh=0;rh<2;rh++)
#pragma unroll
    for (int rw=0;rw<2;rw++){
      int r2 = mh*2+rh, c2 = mw*2+rw;
      int k = (rl-r2+15)*31 + (cl-c2+15);
      s += g_pos[k*6+nh];
    }
  g_rpb[idx] = 0.25f*s;
}

// =============== K2: h2 = lrelu(conv3x3(h1)) ===============
__global__ void __launch_bounds__(256) k_conv3(const float* __restrict__ w2,
                                               const float* __restrict__ b2){
  extern __shared__ float sm2[];
  float* ins = sm2;             // 18*18*37
  float* wsh = sm2 + 11988;     // 9*36*36
  int tid = threadIdx.x;
  int b = blockIdx.z; int hy0 = blockIdx.y*16, wx0 = blockIdx.x*16;
  for (int t=tid;t<18*18*36;t+=256){
    int ci = t%36; int rc = t/36; int col = rc%18; int row = rc/18;
    int gh = hy0+row-1, gw = wx0+col-1;
    float v = 0.f;
    if (gh>=0 && gh<IMG && gw>=0 && gw<IMG)
      v = g_h1[((size_t)(b*IMG+gh)*IMG+gw)*36 + ci];
    ins[(row*18+col)*37+ci] = v;
  }
  for (int t=tid;t<9*36*36;t+=256) wsh[t] = w2[t];
  __syncthreads();
  int tx = tid&15, ty = tid>>4;
  float acc[36];
#pragma unroll
  for (int co=0;co<36;co++) acc[co] = b2[co];
  for (int dy=0;dy<3;dy++)
    for (int dx=0;dx<3;dx++){
      const float* wp = wsh + (dy*3+dx)*36*36;
      const float* ip = ins + ((ty+dy)*18 + tx+dx)*37;
      for (int ci=0;ci<36;ci++){
        float v = ip[ci];
        const float* wr = wp + ci*36;
#pragma unroll
        for (int co=0;co<36;co++) acc[co] += v*wr[co];
      }
    }
  size_t o = ((size_t)(b*IMG+hy0+ty)*IMG + wx0+tx)*36;
  float4* dst = (float4*)(g_h2 + o);
#pragma unroll
  for (int q=0;q<9;q++){
    float4 r; r.x=lrelu(acc[q*4]); r.y=lrelu(acc[q*4+1]); r.z=lrelu(acc[q*4+2]); r.w=lrelu(acc[q*4+3]);
    dst[q]=r;
  }
}

// =============== T2: t_h3: g_qv = (h2 @ w3 + b3) * g_y ===============
__global__ void __launch_bounds__(256,2) t_h3(const float* __restrict__ b3){
  extern __shared__ __align__(16) char smc[];
  __nv_bfloat16* Ab = (__nv_bfloat16*)smc;    // hi @0, lo @3584 elems
  const uint32_t O_B = 7168*2;
  uint32_t sbase = (uint32_t)__cvta_generic_to_shared(smc);
  int tid = threadIdx.x; int lane = tid&31, wid = tid>>5;
  int wm = wid&1, wn = wid>>1;
  int r0 = blockIdx.x*64;

  for (int t=tid; t<2688; t+=256)
    cpa16(sbase + O_B + t*16, (const char*)(g_pk_w3) + t*16);
  CP_COMMIT();

  for (int idx=tid; idx<64*48; idx+=256){
    int px = idx/48, cc = idx - px*48;
    float v = (cc<36) ? g_h2[(size_t)(r0+px)*36 + cc] : 0.f;
    __nv_bfloat16 h,l; cvhl(v,h,l);
    Ab[px*56 + cc]        = h;
    Ab[3584 + px*56 + cc] = l;
  }
  CP_WAIT(0);
  __syncthreads();
  float c[2][6][4];
#pragma unroll
  for (int mt=0;mt<2;mt++)
#pragma unroll
    for (int nt=0;nt<6;nt++)
#pragma unroll
      for (int e=0;e<4;e++) c[mt][nt][e]=0.f;

  mma_pass<56,56,3>(sbase,           sbase + O_B,           c, lane, wm, wn);
  mma_pass<56,56,3>(sbase + 3584*2,  sbase + O_B,           c, lane, wm, wn);
  mma_pass<56,56,3>(sbase,           sbase + O_B + 10752*2, c, lane, wm, wn);
  __syncthreads();
  float* stash = (float*)smc;
#pragma unroll
  for (int mt=0;mt<2;mt++){
    int r1 = wm*32 + mt*16 + (lane>>2);
#pragma unroll
    for (int nt=0;nt<6;nt++){
      int n0 = wn*48 + nt*8 + (lane&3)*2;
      if (n0 < 180){
        float b30=__ldg(b3+n0), b31=__ldg(b3+n0+1);
        stash[r1*181+n0]       = c[mt][nt][0]+b30;
        stash[r1*181+n0+1]     = c[mt][nt][1]+b31;
        stash[(r1+8)*181+n0]   = c[mt][nt][2]+b30;
        stash[(r1+8)*181+n0+1] = c[mt][nt][3]+b31;
      }
    }
  }
  __syncthreads();
  {
    int f = tid;
    int px = f/180, co = f - px*180;
    for (; f < 64*180; f += 256){
      g_qv[(size_t)r0*180 + f] = stash[px*181+co] * g_y[(size_t)r0*180 + f];
      co += 256; if (co >= 180){ co -= 180; px++; if (co >= 180){ co -= 180; px++; } }
    }
  }
}

// =============== K4: per-window attention (512 threads, same smem) ===============
__global__ void __launch_bounds__(512) k_attn(const float* __restrict__ sl_w,
                                              const float* __restrict__ sl_b){
  extern __shared__ float sm4[];
  float* QS = sm4;
  float* VS = sm4 + 256*91;
  float* SC = sm4 + 2*256*91;
  int tid = threadIdx.x;
  int l = tid & 255;
  int h = tid >> 8;          // 0 or 1
  int bw = blockIdx.x;
  int b = bw>>8, wy = (bw>>4)&15, wx = bw&15;
  int gh = wy*16 + (l>>4), gw = wx*16 + (l&15);
  size_t pix = ((size_t)(b*IMG+gh))*IMG + gw;

  // ---- P1: load q,v (2 threads per row: k split 23/22) ----
  {
    const float4* src = (const float4*)(g_qv + pix*180);
#pragma unroll
    for (int kk=0; kk<23; kk++){
      int k = kk + h*23;
      if (k < 45){
        float4 v4 = src[k];
        int c0 = k*4;
        float vals[4] = {v4.x,v4.y,v4.z,v4.w};
#pragma unroll
        for (int e=0;e<4;e++){
          int c = c0+e;
          if (c < 90) QS[l*91+c] = vals[e];
          else        VS[l*91+(c-90)] = vals[e];
        }
      }
    }
  }
  __syncthreads();

  // ---- P2: vp[nh][m][16] ----
  float slw0=sl_w[0], slw1=sl_w[1], slw2=sl_w[2], slw3=sl_w[3], slb=sl_b[0];
  for (int idx=tid; idx<6144; idx+=512){
    int nh = idx>>10; int r = idx & 1023; int m = r>>4; int hd = r&15;
    float val = 0.f;
    if (hd < 15){
      int mh = m>>3, mw = m&7; int ch = nh*15+hd;
      int l00 = (mh*2)*16 + mw*2;
      val = slb + slw0*VS[l00*91+ch]      + slw1*VS[(l00+1)*91+ch]
                + slw2*VS[(l00+16)*91+ch] + slw3*VS[(l00+17)*91+ch];
    }
    SC[idx] = val;
  }
  __syncthreads();

  // ---- P4: corr + xs, 3 heads per thread ----
  {
    float* ydst = g_y + pix*180;
#pragma unroll
    for (int e=0; e<3; e++){
      int nh = h*3 + e;
      float qs[15];
#pragma unroll
      for (int hd=0;hd<15;hd++) qs[hd] = QS[l*91 + nh*15 + hd];
      u64 q2[8];
#pragma unroll
      for (int p=0;p<7;p++) q2[p] = pk2(qs[2*p], qs[2*p+1]);
      q2[7] = pk2(qs[14], 0.f);
      const float* vp = SC + (nh<<10);
      const float* rpbrow = g_rpb + ((size_t)((nh<<8) + l))*64;
      u64 xs2[8];
#pragma unroll
      for (int p=0;p<8;p++) xs2[p]=0ull;
      for (int m0=0;m0<64;m0+=4){
        float4 rb = *(const float4*)(rpbrow + m0);
        float rbv[4] = {rb.x, rb.y, rb.z, rb.w};
#pragma unroll
        for (int t=0;t<4;t++){
          const ulonglong2* vpp = (const ulonglong2*)(vp + ((m0+t)<<4));
          ulonglong2 wA = vpp[0], wB = vpp[1], wC = vpp[2], wD = vpp[3];
          u64 d2 = fmul2(q2[0], wA.x);
          d2 = ffma2(q2[1], wA.y, d2);
          d2 = ffma2(q2[2], wB.x, d2);
          d2 = ffma2(q2[3], wB.y, d2);
          d2 = ffma2(q2[4], wC.x, d2);
          d2 = ffma2(q2[5], wC.y, d2);
          d2 = ffma2(q2[6], wD.x, d2);
          d2 = ffma2(q2[7], wD.y, d2);
          float lo,hi; up2(d2, lo, hi);
          u64 s2 = dup2((lo+hi)*(1.f/15.f) + rbv[t]);
          xs2[0] = ffma2(s2, wA.x, xs2[0]);
          xs2[1] = ffma2(s2, wA.y, xs2[1]);
          xs2[2] = ffma2(s2, wB.x, xs2[2]);
          xs2[3] = ffma2(s2, wB.y, xs2[3]);
          xs2[4] = ffma2(s2, wC.x, xs2[4]);
          xs2[5] = ffma2(s2, wC.y, xs2[5]);
          xs2[6] = ffma2(s2, wD.x, xs2[6]);
          xs2[7] = ffma2(s2, wD.y, xs2[7]);
        }
      }
#pragma unroll
      for (int p=0;p<7;p++){
        float lo,hi; up2(xs2[p], lo, hi);
        ydst[nh*15+2*p] = lo; ydst[nh*15+2*p+1] = hi;
      }
      { float lo,hi; up2(xs2[7], lo, hi); ydst[nh*15+14] = lo; }
    }
  }

  // ---- P3: cmap 6x3 register tiles (450 active threads), c paired ----
  u64 cm2[3][3];
  int cb=0, db=0;
  bool act = (tid < 450);
  if (act){
    cb = (tid/30)*6; db = (tid%30)*3;
#pragma unroll
    for (int i=0;i<3;i++)
#pragma unroll
      for (int j=0;j<3;j++) cm2[i][j]=0ull;
    for (int ll=0; ll<256; ll++){
      u64 qr[3];
#pragma unroll
      for (int i=0;i<3;i++) qr[i] = pk2(QS[ll*91+cb+2*i], QS[ll*91+cb+2*i+1]);
      float vr[3];
#pragma unroll
      for (int j=0;j<3;j++) vr[j] = VS[ll*91+db+j];
#pragma unroll
      for (int j=0;j<3;j++){
        u64 v2 = dup2(vr[j]);
#pragma unroll
        for (int i=0;i<3;i++) cm2[i][j] = ffma2(qr[i], v2, cm2[i][j]);
      }
    }
  }
  __syncthreads();   // vp + QS/VS read phases done -> safe to overwrite SC with cmap^T
  if (act){
#pragma unroll
    for (int i=0;i<3;i++)
#pragma unroll
      for (int j=0;j<3;j++){
        float lo,hi; up2(cm2[i][j], lo, hi);
        SC[(db+j)*92 + cb+2*i]   = lo*(1.f/256.f);
        SC[(db+j)*92 + cb+2*i+1] = hi*(1.f/256.f);
      }
  }
  __syncthreads();

  // ---- P6: xc, channel groups split across halves (h=0: g 0,2,4; h=1: g 1,3) ----
  {
    float* ydst = g_y + pix*180 + 90;
    for (int g=h; g<5; g+=2){
      int c0 = g*18;
      u64 s2[9];
#pragma unroll
      for (int t=0;t<9;t++) s2[t]=0ull;
      for (int d=0; d<90; d++){
        u64 v2 = dup2(VS[l*91+d]);
        const u64* cp = (const u64*)(SC + d*92 + c0);
#pragma unroll
        for (int t=0;t<9;t++) s2[t] = ffma2(v2, cp[t], s2[t]);
      }
#pragma unroll
      for (int t=0;t<9;t++){
        float lo,hi; up2(s2[t], lo, hi);
        *(float2*)(ydst + c0 + 2*t) = make_float2(lo, hi);
      }
    }
  }
}

// =============== T3: t_proj: out = x + RMSNorm(g_y@pjw + pb)*nw ===============
__global__ void __launch_bounds__(256,2) t_proj(const float* __restrict__ x,
                                                const float* __restrict__ pb,
                                                const float* __restrict__ nw,
                                                float* __restrict__ out){
  extern __shared__ __align__(16) char smc[];
  __shared__ float scl[64];
  __nv_bfloat16* Ab = (__nv_bfloat16*)smc;
  const uint32_t O_B0 = 6*4608*2, O_B1 = O_B0 + 13824*2;
  uint32_t sbase = (uint32_t)__cvta_generic_to_shared(smc);
  int tid = threadIdx.x; int lane = tid&31, wid = tid>>5;
  int wm = wid&1, wn = wid>>1;
  int r0 = blockIdx.x*64; int bb = r0>>16; int p0 = r0&65535;

  for (int t=tid; t<1728; t+=256)
    cpa16(sbase + O_B0 + t*16, (const char*)(g_pk_pj) + t*16);
  CP_COMMIT();

  for (int idx=tid; idx<64*192; idx+=256){
    int px = idx/192, cc = idx - px*192;
    float v = (cc<180) ? g_y[(size_t)(r0+px)*180 + cc] : 0.f;
    __nv_bfloat16 h,l; cvhl(v,h,l);
    int t = cc>>6, k = cc&63;
    Ab[t*4608 + px*72 + k]     = h;
    Ab[(t+3)*4608 + px*72 + k] = l;
  }
  float c[2][6][4];
#pragma unroll
  for (int mt=0;mt<2;mt++)
#pragma unroll
    for (int nt=0;nt<6;nt++)
#pragma unroll
      for (int e=0;e<4;e++) c[mt][nt][e]=0.f;

  for (int i=0;i<6;i++){
    uint32_t bo = (i&1) ? O_B1 : O_B0;
    if (i<5){
      uint32_t bn = ((i+1)&1) ? O_B1 : O_B0;
      for (int t=tid; t<1728; t+=256)
        cpa16(sbase + bn + t*16, (const char*)(g_pk_pj + (i+1)*13824) + t*16);
      CP_COMMIT();
      CP_WAIT(1);
    } else {
      CP_WAIT(0);
    }
    __syncthreads();
    if (i<3){
      mma_pass<72,72,4>(sbase + (uint32_t)(i*4608*2),     sbase + bo, c, lane, wm, wn);
      mma_pass<72,72,4>(sbase + (uint32_t)((3+i)*4608*2), sbase + bo, c, lane, wm, wn);
    } else {
      mma_pass<72,72,4>(sbase + (uint32_t)((i-3)*4608*2), sbase + bo, c, lane, wm, wn);
    }
    __syncthreads();
  }
  float* stash = (float*)smc;
#pragma unroll
  for (int mt=0;mt<2;mt++){
    int r1 = wm*32 + mt*16 + (lane>>2);
#pragma unroll
    for (int nt=0;nt<6;nt++){
      int n0 = wn*48 + nt*8 + (lane&3)*2;
      if (n0 < 180){
        float b0=__ldg(pb+n0), b1=__ldg(pb+n0+1);
        stash[r1*181+n0]       = c[mt][nt][0]+b0;
        stash[r1*181+n0+1]     = c[mt][nt][1]+b1;
        stash[(r1+8)*181+n0]   = c[mt][nt][2]+b0;
        stash[(r1+8)*181+n0+1] = c[mt][nt][3]+b1;
      }
    }
  }
  __syncthreads();
  if (tid < 64){
    const float* row = stash + tid*181;
    float s = 0.f;
    for (int cc=0; cc<180; cc++){ float v = row[cc]; s += v*v; }
    scl[tid] = rsqrtf(s*(1.f/180.f) + 1.1920929e-07f);
  }
  __syncthreads();
  {
    int px = tid&63;
    int q = tid>>6;   // 0..3
    float sc = scl[px];
    for (int ci=q; ci<180; ci+=4){
      size_t a = ((size_t)(bb*180+ci))*NPIX + p0 + px;
      out[a] = x[a] + stash[px*181+ci]*sc*__ldg(nw+ci);
    }
  }
}

// =============== launch ===============
extern "C" void kernel_launch(void* const* d_in, const int* in_sizes, int n_in,
                              void* d_out, int out_size){
  const float* x     = (const float*)d_in[0];
  const float* w1    = (const float*)d_in[1];
  const float* b1    = (const float*)d_in[2];
  const float* w2    = (const float*)d_in[3];
  const float* b2    = (const float*)d_in[4];
  const float* w3    = (const float*)d_in[5];
  const float* b3    = (const float*)d_in[6];
  const float* lw    = (const float*)d_in[7];
  const float* lb    = (const float*)d_in[8];
  const float* sl_w  = (const float*)d_in[9];
  const float* sl_b  = (const float*)d_in[10];
  const float* ppw   = (const float*)d_in[11];
  const float* ppb   = (const float*)d_in[12];
  const float* ln1w  = (const float*)d_in[13];
  const float* ln1b  = (const float*)d_in[14];
  const float* l1w   = (const float*)d_in[15];
  const float* l1b   = (const float*)d_in[16];
  const float* ln2w  = (const float*)d_in[17];
  const float* ln2b  = (const float*)d_in[18];
  const float* l2w   = (const float*)d_in[19];
  const float* l2b   = (const float*)d_in[20];
  const float* ln3w  = (const float*)d_in[21];
  const float* ln3b  = (const float*)d_in[22];
  const float* l3w   = (const float*)d_in[23];
  const float* l3b   = (const float*)d_in[24];
  const float* pjw   = (const float*)d_in[25];
  const float* pjb   = (const float*)d_in[26];
  const float* nrmw  = (const float*)d_in[27];
  float* out = (float*)d_out;

  const int SM_K2  = (11988 + 11664) * 4;        // 94608 B
  const int SM_K4  = (2*256*91 + 8280) * 4;      // 219488 B
  const int SM_TL  = 6*4608*2 + 2*13824*2;       // 110592 B
  const int SM_TH  = 7168*2*2 + 2*10752*2;       // 71680 B
  cudaFuncSetAttribute(k_conv3, cudaFuncAttributeMaxDynamicSharedMemorySize, SM_K2);
  cudaFuncSetAttribute(k_attn,  cudaFuncAttributeMaxDynamicSharedMemorySize, SM_K4);
  cudaFuncSetAttribute(t_lin,   cudaFuncAttributeMaxDynamicSharedMemorySize, SM_TL);
  cudaFuncSetAttribute(t_h3,    cudaFuncAttributeMaxDynamicSharedMemorySize, SM_TH);
  cudaFuncSetAttribute(t_proj,  cudaFuncAttributeMaxDynamicSharedMemorySize, SM_TL);

  // k_dfe1 at launch #4 -> profile window inventories it this round
  k_pack180<<<(6*13824+255)/256,256>>>(lw, 0);
  k_pack180<<<(6*13824+255)/256,256>>>(pjw, 1);
  k_pack36<<<(2*10752+255)/256,256>>>(w3);
  k_dfe1<<<TOTPIX/256,256>>>(x, w1, b1);
  t_lin<<<TOTPIX/64,256,SM_TL>>>(x, lb);
  k_pos<<<4,256>>>(ppw, ppb, ln1w, ln1b, l1w, l1b, ln2w, ln2b, l2w, l2b, ln3w, ln3b, l3w, l3b);
  k_rpb<<<384,256>>>();
  k_conv3<<<dim3(16,16,4),256,SM_K2>>>(w2, b2);
  t_h3<<<TOTPIX/64,256,SM_TH>>>(b3);
  k_attn<<<NWIN,512,SM_K4>>>(sl_w, sl_b);
  t_proj<<<TOTPIX/64,256,SM_TL>>>(x, pjb, nrmw, out);
}

// round 9
// speedup vs baseline: 1.3513x; 1.0074x over previous
#include <cuda_runtime.h>
#include <cuda_bf16.h>
#include <math.h>
#include <stdint.h>

#define NBATCH 4
#define NCH    180
#define IMG    256
#define NPIX   (IMG*IMG)            // 65536
#define TOTPIX (NBATCH*NPIX)        // 262144
#define MIDC   36
#define NWIN   1024

// ---- scratch (device globals; no allocation allowed) ----
__device__ float g_h1[(size_t)TOTPIX*MIDC];
__device__ float g_h2[(size_t)TOTPIX*MIDC];
__device__ float g_qv[(size_t)TOTPIX*NCH];
__device__ float g_y [(size_t)TOTPIX*NCH];
__device__ float g_pos[961*6];
__device__ float g_rpb[6*256*64];
__device__ __align__(16) __nv_bfloat16 g_pk_lw[6*13824];  // [192][72] x (Bh0..2,Bl0..2)
__device__ __align__(16) __nv_bfloat16 g_pk_pj[6*13824];
__device__ __align__(16) __nv_bfloat16 g_pk_w3[2*10752];  // [192][56] x (hi,lo)

typedef unsigned long long u64;

__device__ __forceinline__ u64 pk2(float lo, float hi){
  u64 r; asm("mov.b64 %0,{%1,%2};" : "=l"(r) : "f"(lo), "f"(hi)); return r;
}
__device__ __forceinline__ u64 dup2(float v){ return pk2(v, v); }
__device__ __forceinline__ void up2(u64 v, float& lo, float& hi){
  asm("mov.b64 {%0,%1},%2;" : "=f"(lo), "=f"(hi) : "l"(v));
}
__device__ __forceinline__ u64 ffma2(u64 a, u64 b, u64 c){
  u64 d; asm("fma.rn.f32x2 %0,%1,%2,%3;" : "=l"(d) : "l"(a), "l"(b), "l"(c)); return d;
}
__device__ __forceinline__ u64 fmul2(u64 a, u64 b){
  u64 d; asm("mul.rn.f32x2 %0,%1,%2;" : "=l"(d) : "l"(a), "l"(b)); return d;
}
__device__ __forceinline__ float lrelu(float v){ return v >= 0.f ? v : 0.2f*v; }

__device__ __forceinline__ void cvhl(float v, __nv_bfloat16& h, __nv_bfloat16& l){
  h = __float2bfloat16(v);
  l = __float2bfloat16(v - __bfloat162float(h));
}

// ---- portable tensor-core primitives ----
#define MMA16816(c, a, b0, b1) \
  asm volatile("mma.sync.aligned.m16n8k16.row.col.f32.bf16.bf16.f32 " \
    "{%0,%1,%2,%3}, {%4,%5,%6,%7}, {%8,%9}, {%0,%1,%2,%3};" \
    : "+f"((c)[0]), "+f"((c)[1]), "+f"((c)[2]), "+f"((c)[3]) \
    : "r"((a)[0]), "r"((a)[1]), "r"((a)[2]), "r"((a)[3]), "r"(b0), "r"(b1))

__device__ __forceinline__ void ldsm_x4(uint32_t r[4], uint32_t saddr){
  asm volatile("ldmatrix.sync.aligned.m8n8.x4.shared.b16 {%0,%1,%2,%3}, [%4];"
    : "=r"(r[0]),"=r"(r[1]),"=r"(r[2]),"=r"(r[3]) : "r"(saddr));
}
__device__ __forceinline__ void cpa16(uint32_t d, const void* s){
  asm volatile("cp.async.cg.shared.global [%0], [%1], 16;" :: "r"(d), "l"(s));
}
#define CP_COMMIT() asm volatile("cp.async.commit_group;" ::: "memory")
#define CP_WAIT(n)  asm volatile("cp.async.wait_group %0;" :: "n"(n) : "memory")

// pipelined pass: A[64][K]@smem x B[192][K]^T@smem -> c (warp tile 32x48)
template<int SA, int SB, int NKS>
__device__ __forceinline__ void mma_pass(uint32_t aBase, uint32_t bBase,
                                         float c[2][6][4], int lane, int wm, int wn){
  uint32_t aoff[2], boff[3];
  int ar = (lane&7) + ((lane&8)?8:0);
  int ak = (lane&16)?8:0;
#pragma unroll
  for (int mt=0;mt<2;mt++) aoff[mt] = aBase + (uint32_t)(((wm*32+mt*16+ar)*SA + ak)*2);
  int br = (lane&7) + ((lane&16)?8:0);
  int bk = (lane&8)?8:0;
#pragma unroll
  for (int p=0;p<3;p++) boff[p] = bBase + (uint32_t)(((wn*48+p*16+br)*SB + bk)*2);

  uint32_t a[2][2][4], b[2][3][4];
  ldsm_x4(a[0][0], aoff[0]);
  ldsm_x4(a[0][1], aoff[1]);
#pragma unroll
  for (int p=0;p<3;p++) ldsm_x4(b[0][p], boff[p]);
#pragma unroll
  for (int ks=0;ks<NKS;ks++){
    int cur = ks&1, nxt = cur^1;
    if (ks+1 < NKS){
      ldsm_x4(a[nxt][0], aoff[0] + (ks+1)*32);
      ldsm_x4(a[nxt][1], aoff[1] + (ks+1)*32);
#pragma unroll
      for (int p=0;p<3;p++) ldsm_x4(b[nxt][p], boff[p] + (ks+1)*32);
    }
#pragma unroll
    for (int p=0;p<3;p++){
      MMA16816(c[0][2*p],   a[cur][0], b[cur][p][0], b[cur][p][1]);
      MMA16816(c[1][2*p],   a[cur][1], b[cur][p][0], b[cur][p][1]);
      MMA16816(c[0][2*p+1], a[cur][0], b[cur][p][2], b[cur][p][3]);
      MMA16816(c[1][2*p+1], a[cur][1], b[cur][p][2], b[cur][p][3]);
    }
  }
}

__device__ __forceinline__ void ln_relu11(const float* in, const float* w, const float* b, float* out){
  float m = 0.f;
#pragma unroll
  for (int j=0;j<11;j++) m += in[j];
  m *= (1.f/11.f);
  float var = 0.f;
#pragma unroll
  for (int j=0;j<11;j++){ float d = in[j]-m; var += d*d; }
  var *= (1.f/11.f);
  float inv = rsqrtf(var + 1e-5f);
#pragma unroll
  for (int j=0;j<11;j++) out[j] = fmaxf((in[j]-m)*inv*w[j] + b[j], 0.f);
}

// =============== MEGA1: k_dfe1 (blocks 0..1023) + packs + k_pos ===============
// blocks: [0,1024) dfe1; [1024,1348) pack lw; [1348,1672) pack pj;
//         [1672,1756) pack w3; [1756,1760) pos
__global__ void __launch_bounds__(256) mega1(
    const float* __restrict__ x,  const float* __restrict__ w1, const float* __restrict__ b1,
    const float* __restrict__ lw, const float* __restrict__ pjw, const float* __restrict__ w3,
    const float* __restrict__ pw, const float* __restrict__ pb,
    const float* __restrict__ ln1w, const float* __restrict__ ln1b,
    const float* __restrict__ p1w,  const float* __restrict__ p1b,
    const float* __restrict__ ln2w, const float* __restrict__ ln2b,
    const float* __restrict__ p2w,  const float* __restrict__ p2b,
    const float* __restrict__ ln3w, const float* __restrict__ ln3b,
    const float* __restrict__ p3w,  const float* __restrict__ p3b){
  __shared__ __align__(16) float ws[180*36];
  int gid = blockIdx.x;
  int tid = threadIdx.x;

  if (gid < 1024){
    // ---- dfe1 ----
    for (int t=tid;t<180*36;t+=256) ws[t]=w1[t];
    __syncthreads();
    int r = gid*256 + tid;
    int b = r>>16; int p = r&65535;
    const float* xp = x + (size_t)b*NCH*NPIX + p;
    u64 acc2[18];
#pragma unroll
    for (int q=0;q<18;q++) acc2[q] = pk2(b1[2*q], b1[2*q+1]);
    for (int ci=0;ci<180;ci++){
      u64 v2 = dup2(xp[(size_t)ci*NPIX]);
      const ulonglong2* wr = (const ulonglong2*)(ws + ci*36);
#pragma unroll
      for (int q=0;q<9;q++){
        ulonglong2 w = wr[q];
        acc2[2*q]   = ffma2(v2, w.x, acc2[2*q]);
        acc2[2*q+1] = ffma2(v2, w.y, acc2[2*q+1]);
      }
    }
    float2* dst = (float2*)(g_h1 + (size_t)r*36);
#pragma unroll
    for (int q=0;q<18;q++){
      float lo,hi; up2(acc2[q], lo, hi);
      dst[q] = make_float2(lrelu(lo), lrelu(hi));
    }
  } else if (gid < 1672){
    // ---- pack 180x180 (lw or pj) ----
    int which = (gid >= 1348);
    const float* W = which ? pjw : lw;
    __nv_bfloat16* dst = which ? g_pk_pj : g_pk_lw;
    int base = which ? 1348 : 1024;
    int idx = (gid-base)*256 + tid;
    if (idx < 6*13824){
      int cc = idx/13824, r = idx - cc*13824, n = r/72, k = r - n*72;
      int half = cc/3, kc = cc - half*3;
      int kk = kc*64 + k;
      float v = (n<180 && k<64 && kk<180) ? W[kk*180+n] : 0.f;
      __nv_bfloat16 h, l; cvhl(v, h, l);
      dst[idx] = half ? l : h;
    }
  } else if (gid < 1756){
    // ---- pack w3 ----
    int idx = (gid-1672)*256 + tid;
    if (idx < 2*10752){
      int cc = idx/10752, r = idx - cc*10752, n = r/56, k = r - n*56;
      float v = (n<180 && k<36) ? w3[k*180+n] : 0.f;
      __nv_bfloat16 h, l; cvhl(v, h, l);
      g_pk_w3[idx] = cc ? l : h;
    }
  } else {
    // ---- pos MLP ----
    int n = (gid-1756)*256 + tid;
    if (n < 961){
      float i0 = (float)(n/31) - 15.f;
      float i1 = (float)(n%31) - 15.f;
      float p[11], t[11];
#pragma unroll
      for (int j=0;j<11;j++) p[j] = i0*pw[j] + i1*pw[11+j] + pb[j];
      ln_relu11(p, ln1w, ln1b, t);
#pragma unroll
      for (int k=0;k<11;k++){ float s=p1b[k];
#pragma unroll
        for (int j=0;j<11;j++) s += t[j]*p1w[j*11+k]; p[k]=s; }
      ln_relu11(p, ln2w, ln2b, t);
#pragma unroll
      for (int k=0;k<11;k++){ float s=p2b[k];
#pragma unroll
        for (int j=0;j<11;j++) s += t[j]*p2w[j*11+k]; p[k]=s; }
      ln_relu11(p, ln3w, ln3b, t);
#pragma unroll
      for (int k=0;k<6;k++){ float s=p3b[k];
#pragma unroll
        for (int j=0;j<11;j++) s += t[j]*p3w[j*6+k];
        g_pos[n*6+k] = s; }
    }
  }
}

// =============== MEGA2: t_lin (0..4095) + conv3 (4096..5119) + rpb (5120..5503) ===============
__global__ void __launch_bounds__(256,2) mega2(const float* __restrict__ x,
                                               const float* __restrict__ lb,
                                               const float* __restrict__ w2,
                                               const float* __restrict__ b2){
  extern __shared__ __align__(16) char smc[];
  int gid = blockIdx.x;
  int tid = threadIdx.x;

  if (gid < 4096){
    // ---- t_lin ----
    __nv_bfloat16* Ab = (__nv_bfloat16*)smc;
    const uint32_t O_B0 = 6*4608*2, O_B1 = O_B0 + 13824*2;
    uint32_t sbase = (uint32_t)__cvta_generic_to_shared(smc);
    int lane = tid&31, wid = tid>>5;
    int wm = wid&1, wn = wid>>1;
    int r0 = gid*64; int bb = r0>>16; int p0 = r0&65535;

    for (int t=tid; t<1728; t+=256)
      cpa16(sbase + O_B0 + t*16, (const char*)(g_pk_lw) + t*16);
    CP_COMMIT();

    for (int idx=tid; idx<192*64; idx+=256){
      int c = idx>>6, px = idx&63;
      float v = (c<180) ? x[((size_t)(bb*180+c))*NPIX + p0+px] : 0.f;
      __nv_bfloat16 h,l; cvhl(v,h,l);
      int t = c>>6, k = c&63;
      Ab[t*4608 + px*72 + k]     = h;
      Ab[(t+3)*4608 + px*72 + k] = l;
    }
    float c[2][6][4];
#pragma unroll
    for (int mt=0;mt<2;mt++)
#pragma unroll
      for (int nt=0;nt<6;nt++)
#pragma unroll
        for (int e=0;e<4;e++) c[mt][nt][e]=0.f;

    for (int i=0;i<6;i++){
      uint32_t bo = (i&1) ? O_B1 : O_B0;
      if (i<5){
        uint32_t bn = ((i+1)&1) ? O_B1 : O_B0;
        for (int t=tid; t<1728; t+=256)
          cpa16(sbase + bn + t*16, (const char*)(g_pk_lw + (i+1)*13824) + t*16);
        CP_COMMIT();
        CP_WAIT(1);
      } else {
        CP_WAIT(0);
      }
      __syncthreads();
      if (i<3){
        mma_pass<72,72,4>(sbase + (uint32_t)(i*4608*2),     sbase + bo, c, lane, wm, wn);
        mma_pass<72,72,4>(sbase + (uint32_t)((3+i)*4608*2), sbase + bo, c, lane, wm, wn);
      } else {
        mma_pass<72,72,4>(sbase + (uint32_t)((i-3)*4608*2), sbase + bo, c, lane, wm, wn);
      }
      __syncthreads();
    }
    float* stash = (float*)smc;
#pragma unroll
    for (int mt=0;mt<2;mt++){
      int r1 = wm*32 + mt*16 + (lane>>2);
#pragma unroll
      for (int nt=0;nt<6;nt++){
        int n0 = wn*48 + nt*8 + (lane&3)*2;
        if (n0 < 180){
          float bl0=__ldg(lb+n0), bl1=__ldg(lb+n0+1);
          stash[r1*181+n0]       = c[mt][nt][0]+bl0;
          stash[r1*181+n0+1]     = c[mt][nt][1]+bl1;
          stash[(r1+8)*181+n0]   = c[mt][nt][2]+bl0;
          stash[(r1+8)*181+n0+1] = c[mt][nt][3]+bl1;
        }
      }
    }
    __syncthreads();
    int f = tid;
    int px = f/180, co = f - px*180;
    for (; f < 64*180; f += 256){
      g_y[(size_t)r0*180 + f] = stash[px*181+co];
      co += 256; if (co >= 180){ co -= 180; px++; if (co >= 180){ co -= 180; px++; } }
    }
  } else if (gid < 5120){
    // ---- conv3 ----
    float* ins = (float*)smc;          // 18*18*37 floats
    float* wsh = (float*)smc + 11988;  // 9*36*36
    int cg = gid - 4096;
    int b = cg>>8; int hy0 = ((cg>>4)&15)*16, wx0 = (cg&15)*16;
    for (int t=tid;t<18*18*36;t+=256){
      int ci = t%36; int rc = t/36; int col = rc%18; int row = rc/18;
      int gh = hy0+row-1, gw = wx0+col-1;
      float v = 0.f;
      if (gh>=0 && gh<IMG && gw>=0 && gw<IMG)
        v = g_h1[((size_t)(b*IMG+gh)*IMG+gw)*36 + ci];
      ins[(row*18+col)*37+ci] = v;
    }
    for (int t=tid;t<9*36*36;t+=256) wsh[t] = w2[t];
    __syncthreads();
    int tx = tid&15, ty = tid>>4;
    float acc[36];
#pragma unroll
    for (int co=0;co<36;co++) acc[co] = b2[co];
    for (int dy=0;dy<3;dy++)
      for (int dx=0;dx<3;dx++){
        const float* wp = wsh + (dy*3+dx)*36*36;
        const float* ip = ins + ((ty+dy)*18 + tx+dx)*37;
        for (int ci=0;ci<36;ci++){
          float v = ip[ci];
          const float* wr = wp + ci*36;
#pragma unroll
          for (int co=0;co<36;co++) acc[co] += v*wr[co];
        }
      }
    size_t o = ((size_t)(b*IMG+hy0+ty)*IMG + wx0+tx)*36;
    float4* dst = (float4*)(g_h2 + o);
#pragma unroll
    for (int q=0;q<9;q++){
      float4 r; r.x=lrelu(acc[q*4]); r.y=lrelu(acc[q*4+1]); r.z=lrelu(acc[q*4+2]); r.w=lrelu(acc[q*4+3]);
      dst[q]=r;
    }
  } else {
    // ---- rpb ----
    int idx = (gid-5120)*256 + tid;
    if (idx < 6*256*64){
      int nh = idx/16384;
      int r  = idx - nh*16384;
      int l  = r>>6;
      int m  = r&63;
      int rl = l>>4, cl = l&15;
      int mh = m>>3, mw = m&7;
      float s = 0.f;
#pragma unroll
      for (int rh=0;rh<2;rh++)
#pragma unroll
        for (int rw=0;rw<2;rw++){
          int r2 = mh*2+rh, c2 = mw*2+rw;
          int k = (rl-r2+15)*31 + (cl-c2+15);
          s += g_pos[k*6+nh];
        }
      g_rpb[idx] = 0.25f*s;
    }
  }
}

// =============== T2: t_h3: g_qv = (h2 @ w3 + b3) * g_y ===============
__global__ void __launch_bounds__(256,2) t_h3(const float* __restrict__ b3){
  extern __shared__ __align__(16) char smc[];
  __nv_bfloat16* Ab = (__nv_bfloat16*)smc;
  const uint32_t O_B = 7168*2;
  uint32_t sbase = (uint32_t)__cvta_generic_to_shared(smc);
  int tid = threadIdx.x; int lane = tid&31, wid = tid>>5;
  int wm = wid&1, wn = wid>>1;
  int r0 = blockIdx.x*64;

  for (int t=tid; t<2688; t+=256)
    cpa16(sbase + O_B + t*16, (const char*)(g_pk_w3) + t*16);
  CP_COMMIT();

  for (int idx=tid; idx<64*48; idx+=256){
    int px = idx/48, cc = idx - px*48;
    float v = (cc<36) ? g_h2[(size_t)(r0+px)*36 + cc] : 0.f;
    __nv_bfloat16 h,l; cvhl(v,h,l);
    Ab[px*56 + cc]        = h;
    Ab[3584 + px*56 + cc] = l;
  }
  CP_WAIT(0);
  __syncthreads();
  float c[2][6][4];
#pragma unroll
  for (int mt=0;mt<2;mt++)
#pragma unroll
    for (int nt=0;nt<6;nt++)
#pragma unroll
      for (int e=0;e<4;e++) c[mt][nt][e]=0.f;

  mma_pass<56,56,3>(sbase,           sbase + O_B,           c, lane, wm, wn);
  mma_pass<56,56,3>(sbase + 3584*2,  sbase + O_B,           c, lane, wm, wn);
  mma_pass<56,56,3>(sbase,           sbase + O_B + 10752*2, c, lane, wm, wn);
  __syncthreads();
  float* stash = (float*)smc;
#pragma unroll
  for (int mt=0;mt<2;mt++){
    int r1 = wm*32 + mt*16 + (lane>>2);
#pragma unroll
    for (int nt=0;nt<6;nt++){
      int n0 = wn*48 + nt*8 + (lane&3)*2;
      if (n0 < 180){
        float b30=__ldg(b3+n0), b31=__ldg(b3+n0+1);
        stash[r1*181+n0]       = c[mt][nt][0]+b30;
        stash[r1*181+n0+1]     = c[mt][nt][1]+b31;
        stash[(r1+8)*181+n0]   = c[mt][nt][2]+b30;
        stash[(r1+8)*181+n0+1] = c[mt][nt][3]+b31;
      }
    }
  }
  __syncthreads();
  {
    int f = tid;
    int px = f/180, co = f - px*180;
    for (; f < 64*180; f += 256){
      g_qv[(size_t)r0*180 + f] = stash[px*181+co] * g_y[(size_t)r0*180 + f];
      co += 256; if (co >= 180){ co -= 180; px++; if (co >= 180){ co -= 180; px++; } }
    }
  }
}

// =============== K4: per-window attention (512 threads) — LAUNCH #4, gets profiled ===============
__global__ void __launch_bounds__(512) k_attn(const float* __restrict__ sl_w,
                                              const float* __restrict__ sl_b){
  extern __shared__ float sm4[];
  float* QS = sm4;
  float* VS = sm4 + 256*91;
  float* SC = sm4 + 2*256*91;
  int tid = threadIdx.x;
  int l = tid & 255;
  int h = tid >> 8;
  int bw = blockIdx.x;
  int b = bw>>8, wy = (bw>>4)&15, wx = bw&15;
  int gh = wy*16 + (l>>4), gw = wx*16 + (l&15);
  size_t pix = ((size_t)(b*IMG+gh))*IMG + gw;

  {
    const float4* src = (const float4*)(g_qv + pix*180);
#pragma unroll
    for (int kk=0; kk<23; kk++){
      int k = kk + h*23;
      if (k < 45){
        float4 v4 = src[k];
        int c0 = k*4;
        float vals[4] = {v4.x,v4.y,v4.z,v4.w};
#pragma unroll
        for (int e=0;e<4;e++){
          int c = c0+e;
          if (c < 90) QS[l*91+c] = vals[e];
          else        VS[l*91+(c-90)] = vals[e];
        }
      }
    }
  }
  __syncthreads();

  float slw0=sl_w[0], slw1=sl_w[1], slw2=sl_w[2], slw3=sl_w[3], slb=sl_b[0];
  for (int idx=tid; idx<6144; idx+=512){
    int nh = idx>>10; int r = idx & 1023; int m = r>>4; int hd = r&15;
    float val = 0.f;
    if (hd < 15){
      int mh = m>>3, mw = m&7; int ch = nh*15+hd;
      int l00 = (mh*2)*16 + mw*2;
      val = slb + slw0*VS[l00*91+ch]      + slw1*VS[(l00+1)*91+ch]
                + slw2*VS[(l00+16)*91+ch] + slw3*VS[(l00+17)*91+ch];
    }
    SC[idx] = val;
  }
  __syncthreads();

  {
    float* ydst = g_y + pix*180;
#pragma unroll
    for (int e=0; e<3; e++){
      int nh = h*3 + e;
      float qs[15];
#pragma unroll
      for (int hd=0;hd<15;hd++) qs[hd] = QS[l*91 + nh*15 + hd];
      u64 q2[8];
#pragma unroll
      for (int p=0;p<7;p++) q2[p] = pk2(qs[2*p], qs[2*p+1]);
      q2[7] = pk2(qs[14], 0.f);
      const float* vp = SC + (nh<<10);
      const float* rpbrow = g_rpb + ((size_t)((nh<<8) + l))*64;
      u64 xs2[8];
#pragma unroll
      for (int p=0;p<8;p++) xs2[p]=0ull;
      for (int m0=0;m0<64;m0+=4){
        float4 rb = *(const float4*)(rpbrow + m0);
        float rbv[4] = {rb.x, rb.y, rb.z, rb.w};
#pragma unroll
        for (int t=0;t<4;t++){
          const ulonglong2* vpp = (const ulonglong2*)(vp + ((m0+t)<<4));
          ulonglong2 wA = vpp[0], wB = vpp[1], wC = vpp[2], wD = vpp[3];
          u64 d2 = fmul2(q2[0], wA.x);
          d2 = ffma2(q2[1], wA.y, d2);
          d2 = ffma2(q2[2], wB.x, d2);
          d2 = ffma2(q2[3], wB.y, d2);
          d2 = ffma2(q2[4], wC.x, d2);
          d2 = ffma2(q2[5], wC.y, d2);
          d2 = ffma2(q2[6], wD.x, d2);
          d2 = ffma2(q2[7], wD.y, d2);
          float lo,hi; up2(d2, lo, hi);
          u64 s2 = dup2((lo+hi)*(1.f/15.f) + rbv[t]);
          xs2[0] = ffma2(s2, wA.x, xs2[0]);
          xs2[1] = ffma2(s2, wA.y, xs2[1]);
          xs2[2] = ffma2(s2, wB.x, xs2[2]);
          xs2[3] = ffma2(s2, wB.y, xs2[3]);
          xs2[4] = ffma2(s2, wC.x, xs2[4]);
          xs2[5] = ffma2(s2, wC.y, xs2[5]);
          xs2[6] = ffma2(s2, wD.x, xs2[6]);
          xs2[7] = ffma2(s2, wD.y, xs2[7]);
        }
      }
#pragma unroll
      for (int p=0;p<7;p++){
        float lo,hi; up2(xs2[p], lo, hi);
        ydst[nh*15+2*p] = lo; ydst[nh*15+2*p+1] = hi;
      }
      { float lo,hi; up2(xs2[7], lo, hi); ydst[nh*15+14] = lo; }
    }
  }

  u64 cm2[3][3];
  int cb=0, db=0;
  bool act = (tid < 450);
  if (act){
    cb = (tid/30)*6; db = (tid%30)*3;
#pragma unroll
    for (int i=0;i<3;i++)
#pragma unroll
      for (int j=0;j<3;j++) cm2[i][j]=0ull;
    for (int ll=0; ll<256; ll++){
      u64 qr[3];
#pragma unroll
      for (int i=0;i<3;i++) qr[i] = pk2(QS[ll*91+cb+2*i], QS[ll*91+cb+2*i+1]);
      float vr[3];
#pragma unroll
      for (int j=0;j<3;j++) vr[j] = VS[ll*91+db+j];
#pragma unroll
      for (int j=0;j<3;j++){
        u64 v2 = dup2(vr[j]);
#pragma unroll
        for (int i=0;i<3;i++) cm2[i][j] = ffma2(qr[i], v2, cm2[i][j]);
      }
    }
  }
  __syncthreads();
  if (act){
#pragma unroll
    for (int i=0;i<3;i++)
#pragma unroll
      for (int j=0;j<3;j++){
        float lo,hi; up2(cm2[i][j], lo, hi);
        SC[(db+j)*92 + cb+2*i]   = lo*(1.f/256.f);
        SC[(db+j)*92 + cb+2*i+1] = hi*(1.f/256.f);
      }
  }
  __syncthreads();

  {
    float* ydst = g_y + pix*180 + 90;
    for (int g=h; g<5; g+=2){
      int c0 = g*18;
      u64 s2[9];
#pragma unroll
      for (int t=0;t<9;t++) s2[t]=0ull;
      for (int d=0; d<90; d++){
        u64 v2 = dup2(VS[l*91+d]);
        const u64* cp = (const u64*)(SC + d*92 + c0);
#pragma unroll
        for (int t=0;t<9;t++) s2[t] = ffma2(v2, cp[t], s2[t]);
      }
#pragma unroll
      for (int t=0;t<9;t++){
        float lo,hi; up2(s2[t], lo, hi);
        *(float2*)(ydst + c0 + 2*t) = make_float2(lo, hi);
      }
    }
  }
}

// =============== T3: t_proj ===============
__global__ void __launch_bounds__(256,2) t_proj(const float* __restrict__ x,
                                                const float* __restrict__ pb,
                                                const float* __restrict__ nw,
                                                float* __restrict__ out){
  extern __shared__ __align__(16) char smc[];
  __shared__ float scl[64];
  __nv_bfloat16* Ab = (__nv_bfloat16*)smc;
  const uint32_t O_B0 = 6*4608*2, O_B1 = O_B0 + 13824*2;
  uint32_t sbase = (uint32_t)__cvta_generic_to_shared(smc);
  int tid = threadIdx.x; int lane = tid&31, wid = tid>>5;
  int wm = wid&1, wn = wid>>1;
  int r0 = blockIdx.x*64; int bb = r0>>16; int p0 = r0&65535;

  for (int t=tid; t<1728; t+=256)
    cpa16(sbase + O_B0 + t*16, (const char*)(g_pk_pj) + t*16);
  CP_COMMIT();

  for (int idx=tid; idx<64*192; idx+=256){
    int px = idx/192, cc = idx - px*192;
    float v = (cc<180) ? g_y[(size_t)(r0+px)*180 + cc] : 0.f;
    __nv_bfloat16 h,l; cvhl(v,h,l);
    int t = cc>>6, k = cc&63;
    Ab[t*4608 + px*72 + k]     = h;
    Ab[(t+3)*4608 + px*72 + k] = l;
  }
  float c[2][6][4];
#pragma unroll
  for (int mt=0;mt<2;mt++)
#pragma unroll
    for (int nt=0;nt<6;nt++)
#pragma unroll
      for (int e=0;e<4;e++) c[mt][nt][e]=0.f;

  for (int i=0;i<6;i++){
    uint32_t bo = (i&1) ? O_B1 : O_B0;
    if (i<5){
      uint32_t bn = ((i+1)&1) ? O_B1 : O_B0;
      for (int t=tid; t<1728; t+=256)
        cpa16(sbase + bn + t*16, (const char*)(g_pk_pj + (i+1)*13824) + t*16);
      CP_COMMIT();
      CP_WAIT(1);
    } else {
      CP_WAIT(0);
    }
    __syncthreads();
    if (i<3){
      mma_pass<72,72,4>(sbase + (uint32_t)(i*4608*2),     sbase + bo, c, lane, wm, wn);
      mma_pass<72,72,4>(sbase + (uint32_t)((3+i)*4608*2), sbase + bo, c, lane, wm, wn);
    } else {
      mma_pass<72,72,4>(sbase + (uint32_t)((i-3)*4608*2), sbase + bo, c, lane, wm, wn);
    }
    __syncthreads();
  }
  float* stash = (float*)smc;
#pragma unroll
  for (int mt=0;mt<2;mt++){
    int r1 = wm*32 + mt*16 + (lane>>2);
#pragma unroll
    for (int nt=0;nt<6;nt++){
      int n0 = wn*48 + nt*8 + (lane&3)*2;
      if (n0 < 180){
        float b0=__ldg(pb+n0), b1=__ldg(pb+n0+1);
        stash[r1*181+n0]       = c[mt][nt][0]+b0;
        stash[r1*181+n0+1]     = c[mt][nt][1]+b1;
        stash[(r1+8)*181+n0]   = c[mt][nt][2]+b0;
        stash[(r1+8)*181+n0+1] = c[mt][nt][3]+b1;
      }
    }
  }
  __syncthreads();
  if (tid < 64){
    const float* row = stash + tid*181;
    float s = 0.f;
    for (int cc=0; cc<180; cc++){ float v = row[cc]; s += v*v; }
    scl[tid] = rsqrtf(s*(1.f/180.f) + 1.1920929e-07f);
  }
  __syncthreads();
  {
    int px = tid&63;
    int q = tid>>6;
    float sc = scl[px];
    for (int ci=q; ci<180; ci+=4){
      size_t a = ((size_t)(bb*180+ci))*NPIX + p0 + px;
      out[a] = x[a] + stash[px*181+ci]*sc*__ldg(nw+ci);
    }
  }
}

// =============== launch ===============
extern "C" void kernel_launch(void* const* d_in, const int* in_sizes, int n_in,
                              void* d_out, int out_size){
  const float* x     = (const float*)d_in[0];
  const float* w1    = (const float*)d_in[1];
  const float* b1    = (const float*)d_in[2];
  const float* w2    = (const float*)d_in[3];
  const float* b2    = (const float*)d_in[4];
  const float* w3    = (const float*)d_in[5];
  const float* b3    = (const float*)d_in[6];
  const float* lw    = (const float*)d_in[7];
  const float* lb    = (const float*)d_in[8];
  const float* sl_w  = (const float*)d_in[9];
  const float* sl_b  = (const float*)d_in[10];
  const float* ppw   = (const float*)d_in[11];
  const float* ppb   = (const float*)d_in[12];
  const float* ln1w  = (const float*)d_in[13];
  const float* ln1b  = (const float*)d_in[14];
  const float* l1w   = (const float*)d_in[15];
  const float* l1b   = (const float*)d_in[16];
  const float* ln2w  = (const float*)d_in[17];
  const float* ln2b  = (const float*)d_in[18];
  const float* l2w   = (const float*)d_in[19];
  const float* l2b   = (const float*)d_in[20];
  const float* ln3w  = (const float*)d_in[21];
  const float* ln3b  = (const float*)d_in[22];
  const float* l3w   = (const float*)d_in[23];
  const float* l3b   = (const float*)d_in[24];
  const float* pjw   = (const float*)d_in[25];
  const float* pjb   = (const float*)d_in[26];
  const float* nrmw  = (const float*)d_in[27];
  float* out = (float*)d_out;

  const int SM_M2  = 6*4608*2 + 2*13824*2;       // 110592 B (t_lin layout; conv3 fits inside)
  const int SM_K4  = (2*256*91 + 8280) * 4;      // 219488 B
  const int SM_TH  = 7168*2*2 + 2*10752*2;       // 71680 B
  cudaFuncSetAttribute(mega2,   cudaFuncAttributeMaxDynamicSharedMemorySize, SM_M2);
  cudaFuncSetAttribute(k_attn,  cudaFuncAttributeMaxDynamicSharedMemorySize, SM_K4);
  cudaFuncSetAttribute(t_h3,    cudaFuncAttributeMaxDynamicSharedMemorySize, SM_TH);
  cudaFuncSetAttribute(t_proj,  cudaFuncAttributeMaxDynamicSharedMemorySize, SM_M2);

  mega1<<<1760,256>>>(x, w1, b1, lw, pjw, w3,
                      ppw, ppb, ln1w, ln1b, l1w, l1b, ln2w, ln2b, l2w, l2b,
                      ln3w, ln3b, l3w, l3b);
  mega2<<<5504,256,SM_M2>>>(x, lb, w2, b2);
  t_h3<<<TOTPIX/64,256,SM_TH>>>(b3);
  k_attn<<<NWIN,512,SM_K4>>>(sl_w, sl_b);      // launch #4 -> profiled
  t_proj<<<TOTPIX/64,256,SM_M2>>>(x, pjb, nrmw, out);
}